// round 9
// baseline (speedup 1.0000x reference)
#include <cuda_runtime.h>
#include <cuda_bf16.h>
#include <stdint.h>
#include <math.h>

#define NN 40000
#define NE 640000
#define NG 64
#define F_IN 32
#define D_EMB 256
#define D_HID 512
#define D_FC 1024
#define N_CLS 10

// packed bf16 weight-plane segment offsets (elements), layout [k/32][n][k%32]
#define E0 8192
#define E1 73728
#define E2 204800
#define E3 466944
#define E4 729088
#define E5 991232
#define E6 1253376
#define E7 1515520

// ---------------- scratch ----------------
__device__ float g_ew[NE];
__device__ float g_deg[NN];
__device__ int   g_count[NN];
__device__ int   g_rowptr[NN + 1];
__device__ int   g_cursor[NN];
__device__ int   g_csrc[NE];
__device__ float g_cw[NE];
__device__ float g_t[NN * D_HID];
__device__ float g_skip[NN * D_HID];
__device__ float g_pool[NG * D_HID];
__device__ float g_cnt[NG];
__device__ float g_fc[NG * D_FC];
__device__ __nv_bfloat16 g_Bh[E7];
__device__ __nv_bfloat16 g_Bl[E7];
__device__ __nv_bfloat16 g_P0h[NN * D_HID];
__device__ __nv_bfloat16 g_P0l[NN * D_HID];
__device__ __nv_bfloat16 g_P1h[NN * D_HID];
__device__ __nv_bfloat16 g_P1l[NN * D_HID];

// ---------------- small kernels ----------------

__global__ void k_init() {
    int i = blockIdx.x * 256 + threadIdx.x;
    if (i < NN) { g_deg[i] = 1.0f; g_count[i] = 0; }
}

__global__ void k_prep(const float* __restrict__ w0, const float* __restrict__ w1,
                       const float* __restrict__ w2, const float* __restrict__ w3,
                       const float* __restrict__ w4, const float* __restrict__ w5,
                       const float* __restrict__ w6, const float* __restrict__ w7) {
    int i = blockIdx.x * 256 + threadIdx.x;
    if (i >= E7) return;
    const float* W; int N, base;
    if      (i < E0) { W = w0; N = 256; base = 0;  }
    else if (i < E1) { W = w1; N = 256; base = E0; }
    else if (i < E2) { W = w2; N = 512; base = E1; }
    else if (i < E3) { W = w3; N = 512; base = E2; }
    else if (i < E4) { W = w4; N = 512; base = E3; }
    else if (i < E5) { W = w5; N = 512; base = E4; }
    else if (i < E6) { W = w6; N = 512; base = E5; }
    else             { W = w7; N = 512; base = E6; }
    int li = i - base;
    int k = li / N, n = li - k * N;
    float v = W[li];
    __nv_bfloat16 hi = __float2bfloat16(v);
    __nv_bfloat16 lo = __float2bfloat16(v - __bfloat162float(hi));
    int pos = base + (k >> 5) * (N * 32) + n * 32 + (k & 31);
    g_Bh[pos] = hi;
    g_Bl[pos] = lo;
}

__global__ void k_splitx(const float* __restrict__ x,
                         __nv_bfloat16* __restrict__ ph, __nv_bfloat16* __restrict__ pl) {
    int i = blockIdx.x * 256 + threadIdx.x;
    if (i >= NN * F_IN) return;
    float v = x[i];
    __nv_bfloat16 h = __float2bfloat16(v);
    ph[i] = h;
    pl[i] = __float2bfloat16(v - __bfloat162float(h));
}

__global__ void k_edge_hist(const float* __restrict__ ea,
                            const float* __restrict__ w1, const float* __restrict__ b1,
                            const float* __restrict__ w2, const float* __restrict__ b2,
                            const int* __restrict__ dst) {
    int e = blockIdx.x * 256 + threadIdx.x;
    if (e >= NE) return;
    float a = ea[e];
    float s = b2[0];
#pragma unroll
    for (int j = 0; j < 64; j++) {
        float h = fmaxf(fmaf(a, __ldg(&w1[j]), __ldg(&b1[j])), 0.f);
        s = fmaf(h, __ldg(&w2[j]), s);
    }
    float sg = 1.f / (1.f + expf(-s));
    g_ew[e] = sg;
    int d = dst[e];
    atomicAdd(&g_deg[d], sg);
    atomicAdd(&g_count[d], 1);
}

__global__ void k_dinv() {
    int i = blockIdx.x * 256 + threadIdx.x;
    if (i < NN) g_deg[i] = rsqrtf(g_deg[i]);
}

__global__ void __launch_bounds__(1024) k_scan() {
    __shared__ int sp[1024];
    const int t = threadIdx.x;
    const int chunk = (NN + 1023) / 1024;
    const int beg = t * chunk;
    const int end = min(beg + chunk, NN);
    int s = 0;
    for (int i = beg; i < end; i++) s += g_count[i];
    sp[t] = s;
    __syncthreads();
    for (int off = 1; off < 1024; off <<= 1) {
        int v = sp[t];
        int u = (t >= off) ? sp[t - off] : 0;
        __syncthreads();
        sp[t] = v + u;
        __syncthreads();
    }
    int prefix = (t == 0) ? 0 : sp[t - 1];
    for (int i = beg; i < end; i++) {
        g_rowptr[i] = prefix;
        g_cursor[i] = prefix;
        prefix += g_count[i];
    }
    if (t == 1023) g_rowptr[NN] = prefix;
}

__global__ void k_place(const int* __restrict__ src, const int* __restrict__ dst) {
    int e = blockIdx.x * 256 + threadIdx.x;
    if (e >= NE) return;
    int s = src[e];
    float w = g_ew[e] * g_deg[s];
    int pos = atomicAdd(&g_cursor[dst[e]], 1);
    g_csrc[pos] = s;
    g_cw[pos] = w;
}

// ---------------- 4-stage cp.async bf16x3 tensor-core GEMM ----------------
// CTA 128x128, K-chunk 16, 4-stage pipeline. 8 warps of 64x32.
// Planes per stage: Ah | Al | Bh | Bl, pitch 24 bf16 (48B) rows.
#define APITCH2 24
#define PLANE2B (128 * 48)          // 6144
#define STAGE2B (4 * PLANE2B)       // 24576
#define SMEM2B  (4 * STAGE2B)       // 98304

__device__ __forceinline__ void cpa16(uint32_t d, const void* s) {
    asm volatile("cp.async.cg.shared.global [%0], [%1], 16;" :: "r"(d), "l"(s));
}
__device__ __forceinline__ void ldsm4(uint32_t addr, uint32_t* r) {
    asm volatile("ldmatrix.sync.aligned.m8n8.x4.shared.b16 {%0,%1,%2,%3}, [%4];"
                 : "=r"(r[0]), "=r"(r[1]), "=r"(r[2]), "=r"(r[3]) : "r"(addr));
}
__device__ __forceinline__ void mma16816(float* c, const uint32_t* a, uint32_t b0, uint32_t b1) {
    asm volatile("mma.sync.aligned.m16n8k16.row.col.f32.bf16.bf16.f32 "
                 "{%0,%1,%2,%3}, {%4,%5,%6,%7}, {%8,%9}, {%0,%1,%2,%3};"
                 : "+f"(c[0]), "+f"(c[1]), "+f"(c[2]), "+f"(c[3])
                 : "r"(a[0]), "r"(a[1]), "r"(a[2]), "r"(a[3]), "r"(b0), "r"(b1));
}

__global__ void __launch_bounds__(256, 2)
k_bgemm(const __nv_bfloat16* __restrict__ Ah, const __nv_bfloat16* __restrict__ Al,
        const __nv_bfloat16* __restrict__ Bh, const __nv_bfloat16* __restrict__ Bl,
        float* __restrict__ C, int M, int N, int K,
        const float* __restrict__ bias, int relu,
        __nv_bfloat16* __restrict__ outH, __nv_bfloat16* __restrict__ outL) {
    extern __shared__ __align__(128) char smem[];
    const int tid = threadIdx.x;
    const int lane = tid & 31;
    const int warp = tid >> 5;
    const int warpM = (warp & 1) * 64;
    const int warpN = (warp >> 1) * 32;
    const int rowBase = blockIdx.y * 128;
    const int colBase = blockIdx.x * 128;
    uint32_t sb;
    asm("{ .reg .u64 tt; cvta.to.shared.u64 tt, %1; cvt.u32.u64 %0, tt; }"
        : "=r"(sb) : "l"((const void*)smem));

    // ldmatrix per-thread base addresses (stage 0)
    const int q = lane >> 3, r8 = lane & 7;
    const int aRowOff = r8 + (q & 1) * 8;
    const int aKOff = (q >> 1) * 8;
    const int bRowOff = r8 + (q >> 1) * 8;
    const int bKOff = (q & 1) * 8;
    uint32_t baseA[4], baseB[2];
#pragma unroll
    for (int mi = 0; mi < 4; mi++)
        baseA[mi] = sb + ((warpM + mi * 16 + aRowOff) * APITCH2 + aKOff) * 2;
#pragma unroll
    for (int bj = 0; bj < 2; bj++)
        baseB[bj] = sb + 2 * PLANE2B + ((warpN + bj * 16 + bRowOff) * APITCH2 + bKOff) * 2;

    float acc[4][4][4] = {};
    const int nKC = K >> 4;

    auto prefetch = [&](int kc) {
        const uint32_t stb = sb + (kc & 3) * STAGE2B;
#pragma unroll
        for (int i = 0; i < 2; i++) {
            const int op = tid + 256 * i;         // 0..511
            const int plane = op >> 8;            // 0 = hi, 1 = lo
            const int rr = (op & 255) >> 1;
            const int half = op & 1;
            const uint32_t d = stb + rr * 48 + half * 16;
            const int gar = min(rowBase + rr, M - 1);
            const __nv_bfloat16* sA = plane ? Al : Ah;
            cpa16(d + plane * PLANE2B, sA + (size_t)gar * K + kc * 16 + half * 8);
            const __nv_bfloat16* sB = plane ? Bl : Bh;
            const size_t boff = (size_t)(kc >> 1) * ((size_t)N * 32)
                              + (size_t)(colBase + rr) * 32 + (kc & 1) * 16 + half * 8;
            cpa16(d + (2 + plane) * PLANE2B, sB + boff);
        }
        asm volatile("cp.async.commit_group;");
    };

#pragma unroll
    for (int s = 0; s < 3; s++) if (s < nKC) prefetch(s);

    for (int kc = 0; kc < nKC; kc++) {
        if (kc + 3 < nKC) { prefetch(kc + 3); asm volatile("cp.async.wait_group 3;"); }
        else if (kc + 2 < nKC) asm volatile("cp.async.wait_group 2;");
        else if (kc + 1 < nKC) asm volatile("cp.async.wait_group 1;");
        else asm volatile("cp.async.wait_group 0;");
        __syncthreads();
        const uint32_t stOff = (kc & 3) * STAGE2B;
        uint32_t bh[8], bl[8];
        ldsm4(baseB[0] + stOff, bh);
        ldsm4(baseB[1] + stOff, bh + 4);
        ldsm4(baseB[0] + stOff + PLANE2B, bl);
        ldsm4(baseB[1] + stOff + PLANE2B, bl + 4);
#pragma unroll
        for (int mi = 0; mi < 4; mi++) {
            uint32_t ah[4], al[4];
            ldsm4(baseA[mi] + stOff, ah);
            mma16816(acc[mi][0], ah, bh[0], bh[1]);
            mma16816(acc[mi][1], ah, bh[2], bh[3]);
            mma16816(acc[mi][2], ah, bh[4], bh[5]);
            mma16816(acc[mi][3], ah, bh[6], bh[7]);
            mma16816(acc[mi][0], ah, bl[0], bl[1]);
            mma16816(acc[mi][1], ah, bl[2], bl[3]);
            mma16816(acc[mi][2], ah, bl[4], bl[5]);
            mma16816(acc[mi][3], ah, bl[6], bl[7]);
            ldsm4(baseA[mi] + stOff + PLANE2B, al);
            mma16816(acc[mi][0], al, bh[0], bh[1]);
            mma16816(acc[mi][1], al, bh[2], bh[3]);
            mma16816(acc[mi][2], al, bh[4], bh[5]);
            mma16816(acc[mi][3], al, bh[6], bh[7]);
        }
        __syncthreads();
    }

    // ---- epilogue ----
    const int g = lane >> 2, tg = lane & 3;
#pragma unroll
    for (int mi = 0; mi < 4; mi++) {
        const int row0 = rowBase + warpM + mi * 16 + g;
#pragma unroll
        for (int half = 0; half < 2; half++) {
            const int row = row0 + half * 8;
            if (row >= M) continue;
#pragma unroll
            for (int nj = 0; nj < 4; nj++) {
                const int col = colBase + warpN + nj * 8 + tg * 2;
                float v0 = acc[mi][nj][half * 2 + 0];
                float v1 = acc[mi][nj][half * 2 + 1];
                if (bias) { float2 bb = *(const float2*)&bias[col]; v0 += bb.x; v1 += bb.y; }
                if (relu) { v0 = fmaxf(v0, 0.f); v1 = fmaxf(v1, 0.f); }
                if (C) { float2 o = {v0, v1}; *(float2*)&C[(size_t)row * N + col] = o; }
                if (outH) {
                    __nv_bfloat162 h = __floats2bfloat162_rn(v0, v1);
                    __nv_bfloat162 l = __floats2bfloat162_rn(v0 - __bfloat162float(h.x),
                                                             v1 - __bfloat162float(h.y));
                    *(__nv_bfloat162*)&outH[(size_t)row * N + col] = h;
                    *(__nv_bfloat162*)&outL[(size_t)row * N + col] = l;
                }
            }
        }
    }
}

// ---- CSR aggregation: 2 nodes per 256-thread block ----
// o = bias + dinv*(sum w*t[src] + dinv*t[node]); pv = relu-related per mode.
// mode 0: planes = relu(o); mode 1: skip = relu(o), planes = skip;
// mode 2: skip += relu(o), planes = skip. If pool != null, atomically add pv into pool[batch].
__global__ void __launch_bounds__(256)
k_agg(const float4* __restrict__ t, const float* __restrict__ bias, int mode,
      float4* __restrict__ skip,
      __nv_bfloat16* __restrict__ outH, __nv_bfloat16* __restrict__ outL,
      const int* __restrict__ batch, float* __restrict__ pool) {
    const int node = blockIdx.x * 2 + (threadIdx.x >> 7);
    const int c = threadIdx.x & 127;
    const int beg = g_rowptr[node];
    const int end = g_rowptr[node + 1];
    const float di = g_deg[node];

    float ax = 0.f, ay = 0.f, az = 0.f, aw = 0.f;
    int j = beg;
    for (; j + 2 <= end; j += 2) {
        const int s0 = __ldg(&g_csrc[j]);
        const int s1 = __ldg(&g_csrc[j + 1]);
        const float w0 = __ldg(&g_cw[j]);
        const float w1 = __ldg(&g_cw[j + 1]);
        const float4 v0 = t[(size_t)s0 * 128 + c];
        const float4 v1 = t[(size_t)s1 * 128 + c];
        ax = fmaf(w0, v0.x, ax); ay = fmaf(w0, v0.y, ay);
        az = fmaf(w0, v0.z, az); aw = fmaf(w0, v0.w, aw);
        ax = fmaf(w1, v1.x, ax); ay = fmaf(w1, v1.y, ay);
        az = fmaf(w1, v1.z, az); aw = fmaf(w1, v1.w, aw);
    }
    if (j < end) {
        const int s0 = __ldg(&g_csrc[j]);
        const float w0 = __ldg(&g_cw[j]);
        const float4 v0 = t[(size_t)s0 * 128 + c];
        ax = fmaf(w0, v0.x, ax); ay = fmaf(w0, v0.y, ay);
        az = fmaf(w0, v0.z, az); aw = fmaf(w0, v0.w, aw);
    }
    const float4 vs = t[(size_t)node * 128 + c];
    const float4 bb = ((const float4*)bias)[c];
    float4 o;
    o.x = fmaf(di, fmaf(di, vs.x, ax), bb.x);
    o.y = fmaf(di, fmaf(di, vs.y, ay), bb.y);
    o.z = fmaf(di, fmaf(di, vs.z, az), bb.z);
    o.w = fmaf(di, fmaf(di, vs.w, aw), bb.w);
    float4 pv;
    pv.x = fmaxf(o.x, 0.f); pv.y = fmaxf(o.y, 0.f);
    pv.z = fmaxf(o.z, 0.f); pv.w = fmaxf(o.w, 0.f);
    if (mode == 1) {
        skip[(size_t)node * 128 + c] = pv;
    } else if (mode == 2) {
        float4 r = skip[(size_t)node * 128 + c];
        r.x += pv.x; r.y += pv.y; r.z += pv.z; r.w += pv.w;
        skip[(size_t)node * 128 + c] = r;
        pv = r;
    }
    if (outH) {
        const size_t off = (size_t)node * D_HID + c * 4;
        __nv_bfloat162 h0 = __floats2bfloat162_rn(pv.x, pv.y);
        __nv_bfloat162 l0 = __floats2bfloat162_rn(pv.x - __bfloat162float(h0.x),
                                                  pv.y - __bfloat162float(h0.y));
        __nv_bfloat162 h1 = __floats2bfloat162_rn(pv.z, pv.w);
        __nv_bfloat162 l1 = __floats2bfloat162_rn(pv.z - __bfloat162float(h1.x),
                                                  pv.w - __bfloat162float(h1.y));
        *(__nv_bfloat162*)&outH[off] = h0;
        *(__nv_bfloat162*)&outH[off + 2] = h1;
        *(__nv_bfloat162*)&outL[off] = l0;
        *(__nv_bfloat162*)&outL[off + 2] = l1;
    }
    if (pool) {
        const int b = batch[node];
        float* po = pool + b * D_HID + c * 4;
        atomicAdd(po + 0, pv.x);
        atomicAdd(po + 1, pv.y);
        atomicAdd(po + 2, pv.z);
        atomicAdd(po + 3, pv.w);
    }
}

// ---------------- pooling + head ----------------

__global__ void k_zero_pool() {
    int i = blockIdx.x * 256 + threadIdx.x;
    if (i < NG * D_HID) g_pool[i] = 0.f;
    if (i < NG) g_cnt[i] = 0.f;
}

__global__ void k_cnt(const int* __restrict__ batch) {
    int i = blockIdx.x * 256 + threadIdx.x;
    if (i < NN) atomicAdd(&g_cnt[batch[i]], 1.f);
}

__global__ void k_div() {
    int i = blockIdx.x * 256 + threadIdx.x;
    if (i >= NG * D_HID) return;
    g_pool[i] /= fmaxf(g_cnt[i >> 9], 1.f);
}

__global__ void k_fc1(const float* __restrict__ w, const float* __restrict__ b) {
    int idx = blockIdx.x * 256 + threadIdx.x;
    if (idx >= NG * D_FC) return;
    int j = idx & (D_FC - 1);
    int g = idx >> 10;
    float s = b[j];
    const float* p = g_pool + g * D_HID;
#pragma unroll 8
    for (int k = 0; k < D_HID; k++) s = fmaf(p[k], w[k * D_FC + j], s);
    g_fc[idx] = fmaxf(s, 0.f);
}

__global__ void k_head(const float* __restrict__ w, const float* __restrict__ b,
                       float* __restrict__ out) {
    int g = blockIdx.x;
    int j = threadIdx.x;
    if (j >= N_CLS) return;
    float s = b[j];
    const float* p = g_fc + g * D_FC;
    for (int k = 0; k < D_FC; k++) s = fmaf(p[k], w[k * N_CLS + j], s);
    out[g * N_CLS + j] = s;
}

// ---------------- launcher ----------------
extern "C" void kernel_launch(void* const* d_in, const int* in_sizes, int n_in,
                              void* d_out, int out_size) {
    const float* x      = (const float*)d_in[0];
    const int*   ei     = (const int*)d_in[1];
    const float* ea     = (const float*)d_in[2];
    const int*   batch  = (const int*)d_in[3];
    const float* emb_w1 = (const float*)d_in[4];
    const float* emb_b1 = (const float*)d_in[5];
    const float* emb_w2 = (const float*)d_in[6];
    const float* emb_b2 = (const float*)d_in[7];
    const float* ep_w1  = (const float*)d_in[8];
    const float* ep_b1  = (const float*)d_in[9];
    const float* ep_w2  = (const float*)d_in[10];
    const float* ep_b2  = (const float*)d_in[11];
    const float* w_c[6] = {(const float*)d_in[12], (const float*)d_in[14], (const float*)d_in[16],
                           (const float*)d_in[18], (const float*)d_in[20], (const float*)d_in[22]};
    const float* b_c[6] = {(const float*)d_in[13], (const float*)d_in[15], (const float*)d_in[17],
                           (const float*)d_in[19], (const float*)d_in[21], (const float*)d_in[23]};
    const float* fc1_w  = (const float*)d_in[24];
    const float* fc1_b  = (const float*)d_in[25];
    const float* head_w = (const float*)d_in[26];
    const float* head_b = (const float*)d_in[27];

    const int* src = ei;
    const int* dst = ei + NE;

    float *p_t, *p_skip, *p_pool;
    __nv_bfloat16 *p_Bh, *p_Bl, *p_P0h, *p_P0l, *p_P1h, *p_P1l;
    cudaGetSymbolAddress((void**)&p_t,    g_t);
    cudaGetSymbolAddress((void**)&p_skip, g_skip);
    cudaGetSymbolAddress((void**)&p_pool, g_pool);
    cudaGetSymbolAddress((void**)&p_Bh,   g_Bh);
    cudaGetSymbolAddress((void**)&p_Bl,   g_Bl);
    cudaGetSymbolAddress((void**)&p_P0h,  g_P0h);
    cudaGetSymbolAddress((void**)&p_P0l,  g_P0l);
    cudaGetSymbolAddress((void**)&p_P1h,  g_P1h);
    cudaGetSymbolAddress((void**)&p_P1l,  g_P1l);
    const int offW[8] = {0, E0, E1, E2, E3, E4, E5, E6};

    cudaFuncSetAttribute(k_bgemm, cudaFuncAttributeMaxDynamicSharedMemorySize, SMEM2B);

    const int EB = (NE + 255) / 256;
    const int NB = (NN + 255) / 256;
    const __nv_bfloat16* BF0 = (const __nv_bfloat16*)0;
    __nv_bfloat16* BFW0 = (__nv_bfloat16*)0;

#define BGEMM(AH, AL, Cout, OFFI, M_, N_, K_, BIAS, RELU, OH, OL)                            \
    k_bgemm<<<dim3((N_) / 128, ((M_) + 127) / 128), 256, SMEM2B>>>(                          \
        (AH), (AL), p_Bh + offW[OFFI], p_Bl + offW[OFFI], (Cout), (M_), (N_), (K_),          \
        (BIAS), (RELU), (OH), (OL))
#define AGG(BIAS, MODE, OH, OL, POOL)                                                        \
    k_agg<<<NN / 2, 256>>>((const float4*)p_t, (BIAS), (MODE), (float4*)p_skip,              \
                           (OH), (OL), batch, (POOL))

    k_prep<<<(E7 + 255) / 256, 256>>>(emb_w1, emb_w2, w_c[0], w_c[1], w_c[2], w_c[3], w_c[4], w_c[5]);
    k_splitx<<<(NN * F_IN + 255) / 256, 256>>>(x, p_P0h, p_P0l);
    BGEMM(p_P0h, p_P0l, (float*)0, 0, NN, D_EMB, F_IN,  emb_b1, 1, p_P1h, p_P1l); // emb1
    BGEMM(p_P1h, p_P1l, (float*)0, 1, NN, D_EMB, D_EMB, emb_b2, 1, p_P0h, p_P0l); // emb2
    BGEMM(p_P0h, p_P0l, p_t, 2, NN, D_HID, D_EMB, (const float*)0, 0, BFW0, BFW0); // conv1 xform
    k_init<<<NB, 256>>>();
    k_edge_hist<<<EB, 256>>>(ea, ep_w1, ep_b1, ep_w2, ep_b2, dst);
    k_dinv<<<NB, 256>>>();
    k_scan<<<1, 1024>>>();
    k_place<<<EB, 256>>>(src, dst);
    k_zero_pool<<<(NG * D_HID + 255) / 256, 256>>>();
    k_cnt<<<NB, 256>>>(batch);
    AGG(b_c[0], 1, p_P1h, p_P1l, (float*)0);                                      // conv1 agg

    BGEMM(p_P1h, p_P1l, p_t, 3, NN, D_HID, D_HID, (const float*)0, 0, BFW0, BFW0);
    AGG(b_c[1], 0, p_P0h, p_P0l, (float*)0);                                      // conv2
    BGEMM(p_P0h, p_P0l, p_t, 4, NN, D_HID, D_HID, (const float*)0, 0, BFW0, BFW0);
    AGG(b_c[2], 2, p_P1h, p_P1l, (float*)0);                                      // conv3
    BGEMM(p_P1h, p_P1l, p_t, 5, NN, D_HID, D_HID, (const float*)0, 0, BFW0, BFW0);
    AGG(b_c[3], 0, p_P0h, p_P0l, (float*)0);                                      // conv4
    BGEMM(p_P0h, p_P0l, p_t, 6, NN, D_HID, D_HID, (const float*)0, 0, BFW0, BFW0);
    AGG(b_c[4], 0, p_P1h, p_P1l, (float*)0);                                      // conv5
    BGEMM(p_P1h, p_P1l, p_t, 7, NN, D_HID, D_HID, (const float*)0, 0, BFW0, BFW0);
    AGG(b_c[5], 2, BFW0, BFW0, p_pool);                                           // conv6 + pool
#undef AGG
#undef BGEMM

    k_div<<<(NG * D_HID + 255) / 256, 256>>>();
    k_fc1<<<(NG * D_FC + 255) / 256, 256>>>(fc1_w, fc1_b);
    k_head<<<NG, 32>>>(head_w, head_b, (float*)d_out);
}

// round 10
// speedup vs baseline: 1.1204x; 1.1204x over previous
#include <cuda_runtime.h>
#include <cuda_bf16.h>
#include <stdint.h>
#include <math.h>

#define NN 40000
#define NE 640000
#define NG 64
#define F_IN 32
#define D_EMB 256
#define D_HID 512
#define D_FC 1024
#define N_CLS 10

// packed bf16 weight-plane segment offsets (elements), layout [k/32][n][k%32]
#define E0 8192
#define E1 73728
#define E2 204800
#define E3 466944
#define E4 729088
#define E5 991232
#define E6 1253376
#define E7 1515520

// ---------------- scratch ----------------
__device__ float g_ew[NE];
__device__ float g_deg[NN];
__device__ int   g_count[NN];
__device__ int   g_rowptr[NN + 1];
__device__ int   g_cursor[NN];
__device__ int   g_csrc[NE];
__device__ float g_cw[NE];
__device__ float g_t[NN * D_HID];
__device__ float g_skip[NN * D_HID];
__device__ float g_pool[NG * D_HID];
__device__ float g_cnt[NG];
__device__ float g_fc[NG * D_FC];
__device__ __nv_bfloat16 g_Bh[E7];
__device__ __nv_bfloat16 g_Bl[E7];
__device__ __nv_bfloat16 g_P0h[NN * D_HID];
__device__ __nv_bfloat16 g_P0l[NN * D_HID];
__device__ __nv_bfloat16 g_P1h[NN * D_HID];
__device__ __nv_bfloat16 g_P1l[NN * D_HID];

// ---------------- small kernels ----------------

__global__ void k_init() {
    int i = blockIdx.x * 256 + threadIdx.x;
    if (i < NN) { g_deg[i] = 1.0f; g_count[i] = 0; }
}

__global__ void k_prep(const float* __restrict__ w0, const float* __restrict__ w1,
                       const float* __restrict__ w2, const float* __restrict__ w3,
                       const float* __restrict__ w4, const float* __restrict__ w5,
                       const float* __restrict__ w6, const float* __restrict__ w7) {
    int i = blockIdx.x * 256 + threadIdx.x;
    if (i >= E7) return;
    const float* W; int N, base;
    if      (i < E0) { W = w0; N = 256; base = 0;  }
    else if (i < E1) { W = w1; N = 256; base = E0; }
    else if (i < E2) { W = w2; N = 512; base = E1; }
    else if (i < E3) { W = w3; N = 512; base = E2; }
    else if (i < E4) { W = w4; N = 512; base = E3; }
    else if (i < E5) { W = w5; N = 512; base = E4; }
    else if (i < E6) { W = w6; N = 512; base = E5; }
    else             { W = w7; N = 512; base = E6; }
    int li = i - base;
    int k = li / N, n = li - k * N;
    float v = W[li];
    __nv_bfloat16 hi = __float2bfloat16(v);
    __nv_bfloat16 lo = __float2bfloat16(v - __bfloat162float(hi));
    int pos = base + (k >> 5) * (N * 32) + n * 32 + (k & 31);
    g_Bh[pos] = hi;
    g_Bl[pos] = lo;
}

__global__ void k_splitx(const float* __restrict__ x,
                         __nv_bfloat16* __restrict__ ph, __nv_bfloat16* __restrict__ pl) {
    int i = blockIdx.x * 256 + threadIdx.x;
    if (i >= NN * F_IN) return;
    float v = x[i];
    __nv_bfloat16 h = __float2bfloat16(v);
    ph[i] = h;
    pl[i] = __float2bfloat16(v - __bfloat162float(h));
}

__global__ void k_edge_hist(const float* __restrict__ ea,
                            const float* __restrict__ w1, const float* __restrict__ b1,
                            const float* __restrict__ w2, const float* __restrict__ b2,
                            const int* __restrict__ dst) {
    int e = blockIdx.x * 256 + threadIdx.x;
    if (e >= NE) return;
    float a = ea[e];
    float s = b2[0];
#pragma unroll
    for (int j = 0; j < 64; j++) {
        float h = fmaxf(fmaf(a, __ldg(&w1[j]), __ldg(&b1[j])), 0.f);
        s = fmaf(h, __ldg(&w2[j]), s);
    }
    float sg = 1.f / (1.f + expf(-s));
    g_ew[e] = sg;
    int d = dst[e];
    atomicAdd(&g_deg[d], sg);
    atomicAdd(&g_count[d], 1);
}

__global__ void k_dinv() {
    int i = blockIdx.x * 256 + threadIdx.x;
    if (i < NN) g_deg[i] = rsqrtf(g_deg[i]);
}

__global__ void __launch_bounds__(1024) k_scan() {
    __shared__ int sp[1024];
    const int t = threadIdx.x;
    const int chunk = (NN + 1023) / 1024;
    const int beg = t * chunk;
    const int end = min(beg + chunk, NN);
    int s = 0;
    for (int i = beg; i < end; i++) s += g_count[i];
    sp[t] = s;
    __syncthreads();
    for (int off = 1; off < 1024; off <<= 1) {
        int v = sp[t];
        int u = (t >= off) ? sp[t - off] : 0;
        __syncthreads();
        sp[t] = v + u;
        __syncthreads();
    }
    int prefix = (t == 0) ? 0 : sp[t - 1];
    for (int i = beg; i < end; i++) {
        g_rowptr[i] = prefix;
        g_cursor[i] = prefix;
        prefix += g_count[i];
    }
    if (t == 1023) g_rowptr[NN] = prefix;
}

__global__ void k_place(const int* __restrict__ src, const int* __restrict__ dst) {
    int e = blockIdx.x * 256 + threadIdx.x;
    if (e >= NE) return;
    int s = src[e];
    float w = g_ew[e] * g_deg[s];
    int pos = atomicAdd(&g_cursor[dst[e]], 1);
    g_csrc[pos] = s;
    g_cw[pos] = w;
}

// ---------------- cp.async double-buffered bf16x3 tensor-core GEMM (R8 config) ----------------
// CTA 128x128, K-chunk 32, 2-stage pipeline. 8 warps of 64x32. Pitch 40 bf16 rows.
#define APITCH 40
#define PLANEB 10240                // 128 * 80
#define STAGEB (4 * PLANEB)         // Ah | Al | Bh | Bl
#define SMEMB  (2 * STAGEB)         // 81920

__device__ __forceinline__ void cpa16(uint32_t d, const void* s) {
    asm volatile("cp.async.ca.shared.global [%0], [%1], 16;" :: "r"(d), "l"(s));
}
__device__ __forceinline__ void ldsm4(uint32_t addr, uint32_t* r) {
    asm volatile("ldmatrix.sync.aligned.m8n8.x4.shared.b16 {%0,%1,%2,%3}, [%4];"
                 : "=r"(r[0]), "=r"(r[1]), "=r"(r[2]), "=r"(r[3]) : "r"(addr));
}
__device__ __forceinline__ void mma16816(float* c, const uint32_t* a, uint32_t b0, uint32_t b1) {
    asm volatile("mma.sync.aligned.m16n8k16.row.col.f32.bf16.bf16.f32 "
                 "{%0,%1,%2,%3}, {%4,%5,%6,%7}, {%8,%9}, {%0,%1,%2,%3};"
                 : "+f"(c[0]), "+f"(c[1]), "+f"(c[2]), "+f"(c[3])
                 : "r"(a[0]), "r"(a[1]), "r"(a[2]), "r"(a[3]), "r"(b0), "r"(b1));
}

__global__ void __launch_bounds__(256, 2)
k_bgemm(const __nv_bfloat16* __restrict__ Ah, const __nv_bfloat16* __restrict__ Al,
        const __nv_bfloat16* __restrict__ Bh, const __nv_bfloat16* __restrict__ Bl,
        float* __restrict__ C, int M, int N, int K,
        const float* __restrict__ bias, int relu,
        __nv_bfloat16* __restrict__ outH, __nv_bfloat16* __restrict__ outL) {
    extern __shared__ __align__(128) char smem[];
    const int tid = threadIdx.x;
    const int lane = tid & 31;
    const int warp = tid >> 5;
    const int warpM = (warp & 1) * 64;
    const int warpN = (warp >> 1) * 32;
    const int rowBase = blockIdx.y * 128;
    const int colBase = blockIdx.x * 128;
    uint32_t sb;
    asm("{ .reg .u64 tt; cvta.to.shared.u64 tt, %1; cvt.u32.u64 %0, tt; }"
        : "=r"(sb) : "l"((const void*)smem));

    const int q = lane >> 3, r8 = lane & 7;
    const int aRowOff = r8 + (q & 1) * 8;
    const int aKOff = (q >> 1) * 8;
    const int bRowOff = r8 + (q >> 1) * 8;
    const int bKOff = (q & 1) * 8;
    uint32_t baseA[4], baseB[2];
#pragma unroll
    for (int mi = 0; mi < 4; mi++)
        baseA[mi] = sb + ((warpM + mi * 16 + aRowOff) * APITCH + aKOff) * 2;
#pragma unroll
    for (int bj = 0; bj < 2; bj++)
        baseB[bj] = sb + 2 * PLANEB + ((warpN + bj * 16 + bRowOff) * APITCH + bKOff) * 2;

    float acc[4][4][4] = {};
    const int nKC = K >> 5;

    auto prefetch = [&](int stage, int kc) {
        const uint32_t stb = sb + stage * STAGEB;
#pragma unroll
        for (int i = 0; i < 2; i++) {
            const int chunk = tid + 256 * i;
            const int row = chunk >> 2, o = chunk & 3;
            const int gar = min(rowBase + row, M - 1);
            const size_t aoff = (size_t)gar * K + kc * 32 + o * 8;
            const uint32_t sd = stb + row * 80 + o * 16;
            cpa16(sd, Ah + aoff);
            cpa16(sd + PLANEB, Al + aoff);
            const size_t boff = (size_t)kc * ((size_t)N * 32) + (size_t)(colBase + row) * 32 + o * 8;
            cpa16(sd + 2 * PLANEB, Bh + boff);
            cpa16(sd + 3 * PLANEB, Bl + boff);
        }
        asm volatile("cp.async.commit_group;");
    };

    prefetch(0, 0);
    for (int kc = 0; kc < nKC; kc++) {
        const bool more = (kc + 1 < nKC);
        if (more) prefetch((kc + 1) & 1, kc + 1);
        if (more) asm volatile("cp.async.wait_group 1;");
        else      asm volatile("cp.async.wait_group 0;");
        __syncthreads();
        const uint32_t stOff = (kc & 1) * STAGEB;
#pragma unroll
        for (int ks = 0; ks < 32; ks += 16) {
            uint32_t bh[8], bl[8];
            ldsm4(baseB[0] + stOff + ks * 2, bh);
            ldsm4(baseB[1] + stOff + ks * 2, bh + 4);
            ldsm4(baseB[0] + stOff + PLANEB + ks * 2, bl);
            ldsm4(baseB[1] + stOff + PLANEB + ks * 2, bl + 4);
#pragma unroll
            for (int mi = 0; mi < 4; mi++) {
                uint32_t ah[4], al[4];
                ldsm4(baseA[mi] + stOff + ks * 2, ah);
                mma16816(acc[mi][0], ah, bh[0], bh[1]);
                mma16816(acc[mi][1], ah, bh[2], bh[3]);
                mma16816(acc[mi][2], ah, bh[4], bh[5]);
                mma16816(acc[mi][3], ah, bh[6], bh[7]);
                mma16816(acc[mi][0], ah, bl[0], bl[1]);
                mma16816(acc[mi][1], ah, bl[2], bl[3]);
                mma16816(acc[mi][2], ah, bl[4], bl[5]);
                mma16816(acc[mi][3], ah, bl[6], bl[7]);
                ldsm4(baseA[mi] + stOff + PLANEB + ks * 2, al);
                mma16816(acc[mi][0], al, bh[0], bh[1]);
                mma16816(acc[mi][1], al, bh[2], bh[3]);
                mma16816(acc[mi][2], al, bh[4], bh[5]);
                mma16816(acc[mi][3], al, bh[6], bh[7]);
            }
        }
        __syncthreads();
    }

    // ---- epilogue (nullable C, optional bf16 plane output) ----
    const int g = lane >> 2, tg = lane & 3;
#pragma unroll
    for (int mi = 0; mi < 4; mi++) {
        const int row0 = rowBase + warpM + mi * 16 + g;
#pragma unroll
        for (int half = 0; half < 2; half++) {
            const int row = row0 + half * 8;
            if (row >= M) continue;
#pragma unroll
            for (int nj = 0; nj < 4; nj++) {
                const int col = colBase + warpN + nj * 8 + tg * 2;
                float v0 = acc[mi][nj][half * 2 + 0];
                float v1 = acc[mi][nj][half * 2 + 1];
                if (bias) { float2 bb = *(const float2*)&bias[col]; v0 += bb.x; v1 += bb.y; }
                if (relu) { v0 = fmaxf(v0, 0.f); v1 = fmaxf(v1, 0.f); }
                if (C) { float2 o = {v0, v1}; *(float2*)&C[(size_t)row * N + col] = o; }
                if (outH) {
                    __nv_bfloat162 h = __floats2bfloat162_rn(v0, v1);
                    __nv_bfloat162 l = __floats2bfloat162_rn(v0 - __bfloat162float(h.x),
                                                             v1 - __bfloat162float(h.y));
                    *(__nv_bfloat162*)&outH[(size_t)row * N + col] = h;
                    *(__nv_bfloat162*)&outL[(size_t)row * N + col] = l;
                }
            }
        }
    }
}

// ---- CSR aggregation: 2 nodes per 256-thread block, fused pooling option ----
__global__ void __launch_bounds__(256)
k_agg(const float4* __restrict__ t, const float* __restrict__ bias, int mode,
      float4* __restrict__ skip,
      __nv_bfloat16* __restrict__ outH, __nv_bfloat16* __restrict__ outL,
      const int* __restrict__ batch, float* __restrict__ pool) {
    const int node = blockIdx.x * 2 + (threadIdx.x >> 7);
    const int c = threadIdx.x & 127;
    const int beg = g_rowptr[node];
    const int end = g_rowptr[node + 1];
    const float di = g_deg[node];

    float ax = 0.f, ay = 0.f, az = 0.f, aw = 0.f;
    int j = beg;
    for (; j + 2 <= end; j += 2) {
        const int s0 = __ldg(&g_csrc[j]);
        const int s1 = __ldg(&g_csrc[j + 1]);
        const float w0 = __ldg(&g_cw[j]);
        const float w1 = __ldg(&g_cw[j + 1]);
        const float4 v0 = t[(size_t)s0 * 128 + c];
        const float4 v1 = t[(size_t)s1 * 128 + c];
        ax = fmaf(w0, v0.x, ax); ay = fmaf(w0, v0.y, ay);
        az = fmaf(w0, v0.z, az); aw = fmaf(w0, v0.w, aw);
        ax = fmaf(w1, v1.x, ax); ay = fmaf(w1, v1.y, ay);
        az = fmaf(w1, v1.z, az); aw = fmaf(w1, v1.w, aw);
    }
    if (j < end) {
        const int s0 = __ldg(&g_csrc[j]);
        const float w0 = __ldg(&g_cw[j]);
        const float4 v0 = t[(size_t)s0 * 128 + c];
        ax = fmaf(w0, v0.x, ax); ay = fmaf(w0, v0.y, ay);
        az = fmaf(w0, v0.z, az); aw = fmaf(w0, v0.w, aw);
    }
    const float4 vs = t[(size_t)node * 128 + c];
    const float4 bb = ((const float4*)bias)[c];
    float4 o;
    o.x = fmaf(di, fmaf(di, vs.x, ax), bb.x);
    o.y = fmaf(di, fmaf(di, vs.y, ay), bb.y);
    o.z = fmaf(di, fmaf(di, vs.z, az), bb.z);
    o.w = fmaf(di, fmaf(di, vs.w, aw), bb.w);
    float4 pv;
    pv.x = fmaxf(o.x, 0.f); pv.y = fmaxf(o.y, 0.f);
    pv.z = fmaxf(o.z, 0.f); pv.w = fmaxf(o.w, 0.f);
    if (mode == 1) {
        skip[(size_t)node * 128 + c] = pv;
    } else if (mode == 2) {
        float4 r = skip[(size_t)node * 128 + c];
        r.x += pv.x; r.y += pv.y; r.z += pv.z; r.w += pv.w;
        skip[(size_t)node * 128 + c] = r;
        pv = r;
    }
    if (outH) {
        const size_t off = (size_t)node * D_HID + c * 4;
        __nv_bfloat162 h0 = __floats2bfloat162_rn(pv.x, pv.y);
        __nv_bfloat162 l0 = __floats2bfloat162_rn(pv.x - __bfloat162float(h0.x),
                                                  pv.y - __bfloat162float(h0.y));
        __nv_bfloat162 h1 = __floats2bfloat162_rn(pv.z, pv.w);
        __nv_bfloat162 l1 = __floats2bfloat162_rn(pv.z - __bfloat162float(h1.x),
                                                  pv.w - __bfloat162float(h1.y));
        *(__nv_bfloat162*)&outH[off] = h0;
        *(__nv_bfloat162*)&outH[off + 2] = h1;
        *(__nv_bfloat162*)&outL[off] = l0;
        *(__nv_bfloat162*)&outL[off + 2] = l1;
    }
    if (pool) {
        const int b = batch[node];
        float* po = pool + b * D_HID + c * 4;
        atomicAdd(po + 0, pv.x);
        atomicAdd(po + 1, pv.y);
        atomicAdd(po + 2, pv.z);
        atomicAdd(po + 3, pv.w);
    }
}

// ---------------- pooling + head ----------------

__global__ void k_zero_pool() {
    int i = blockIdx.x * 256 + threadIdx.x;
    if (i < NG * D_HID) g_pool[i] = 0.f;
    if (i < NG) g_cnt[i] = 0.f;
}

__global__ void k_cnt(const int* __restrict__ batch) {
    int i = blockIdx.x * 256 + threadIdx.x;
    if (i < NN) atomicAdd(&g_cnt[batch[i]], 1.f);
}

__global__ void k_div() {
    int i = blockIdx.x * 256 + threadIdx.x;
    if (i >= NG * D_HID) return;
    g_pool[i] /= fmaxf(g_cnt[i >> 9], 1.f);
}

__global__ void k_fc1(const float* __restrict__ w, const float* __restrict__ b) {
    int idx = blockIdx.x * 256 + threadIdx.x;
    if (idx >= NG * D_FC) return;
    int j = idx & (D_FC - 1);
    int g = idx >> 10;
    float s = b[j];
    const float* p = g_pool + g * D_HID;
#pragma unroll 8
    for (int k = 0; k < D_HID; k++) s = fmaf(p[k], w[k * D_FC + j], s);
    g_fc[idx] = fmaxf(s, 0.f);
}

__global__ void k_head(const float* __restrict__ w, const float* __restrict__ b,
                       float* __restrict__ out) {
    int g = blockIdx.x;
    int j = threadIdx.x;
    if (j >= N_CLS) return;
    float s = b[j];
    const float* p = g_fc + g * D_FC;
    for (int k = 0; k < D_FC; k++) s = fmaf(p[k], w[k * N_CLS + j], s);
    out[g * N_CLS + j] = s;
}

// ---------------- launcher ----------------
extern "C" void kernel_launch(void* const* d_in, const int* in_sizes, int n_in,
                              void* d_out, int out_size) {
    const float* x      = (const float*)d_in[0];
    const int*   ei     = (const int*)d_in[1];
    const float* ea     = (const float*)d_in[2];
    const int*   batch  = (const int*)d_in[3];
    const float* emb_w1 = (const float*)d_in[4];
    const float* emb_b1 = (const float*)d_in[5];
    const float* emb_w2 = (const float*)d_in[6];
    const float* emb_b2 = (const float*)d_in[7];
    const float* ep_w1  = (const float*)d_in[8];
    const float* ep_b1  = (const float*)d_in[9];
    const float* ep_w2  = (const float*)d_in[10];
    const float* ep_b2  = (const float*)d_in[11];
    const float* w_c[6] = {(const float*)d_in[12], (const float*)d_in[14], (const float*)d_in[16],
                           (const float*)d_in[18], (const float*)d_in[20], (const float*)d_in[22]};
    const float* b_c[6] = {(const float*)d_in[13], (const float*)d_in[15], (const float*)d_in[17],
                           (const float*)d_in[19], (const float*)d_in[21], (const float*)d_in[23]};
    const float* fc1_w  = (const float*)d_in[24];
    const float* fc1_b  = (const float*)d_in[25];
    const float* head_w = (const float*)d_in[26];
    const float* head_b = (const float*)d_in[27];

    const int* src = ei;
    const int* dst = ei + NE;

    float *p_t, *p_skip, *p_pool;
    __nv_bfloat16 *p_Bh, *p_Bl, *p_P0h, *p_P0l, *p_P1h, *p_P1l;
    cudaGetSymbolAddress((void**)&p_t,    g_t);
    cudaGetSymbolAddress((void**)&p_skip, g_skip);
    cudaGetSymbolAddress((void**)&p_pool, g_pool);
    cudaGetSymbolAddress((void**)&p_Bh,   g_Bh);
    cudaGetSymbolAddress((void**)&p_Bl,   g_Bl);
    cudaGetSymbolAddress((void**)&p_P0h,  g_P0h);
    cudaGetSymbolAddress((void**)&p_P0l,  g_P0l);
    cudaGetSymbolAddress((void**)&p_P1h,  g_P1h);
    cudaGetSymbolAddress((void**)&p_P1l,  g_P1l);
    const int offW[8] = {0, E0, E1, E2, E3, E4, E5, E6};

    cudaFuncSetAttribute(k_bgemm, cudaFuncAttributeMaxDynamicSharedMemorySize, SMEMB);

    const int EB = (NE + 255) / 256;
    const int NB = (NN + 255) / 256;
    __nv_bfloat16* BFW0 = (__nv_bfloat16*)0;

#define BGEMM(AH, AL, Cout, OFFI, M_, N_, K_, BIAS, RELU, OH, OL)                            \
    k_bgemm<<<dim3((N_) / 128, ((M_) + 127) / 128), 256, SMEMB>>>(                           \
        (AH), (AL), p_Bh + offW[OFFI], p_Bl + offW[OFFI], (Cout), (M_), (N_), (K_),          \
        (BIAS), (RELU), (OH), (OL))
#define AGG(BIAS, MODE, OH, OL, POOL)                                                        \
    k_agg<<<NN / 2, 256>>>((const float4*)p_t, (BIAS), (MODE), (float4*)p_skip,              \
                           (OH), (OL), batch, (POOL))

    k_prep<<<(E7 + 255) / 256, 256>>>(emb_w1, emb_w2, w_c[0], w_c[1], w_c[2], w_c[3], w_c[4], w_c[5]);
    k_splitx<<<(NN * F_IN + 255) / 256, 256>>>(x, p_P0h, p_P0l);
    BGEMM(p_P0h, p_P0l, (float*)0, 0, NN, D_EMB, F_IN,  emb_b1, 1, p_P1h, p_P1l); // emb1
    BGEMM(p_P1h, p_P1l, (float*)0, 1, NN, D_EMB, D_EMB, emb_b2, 1, p_P0h, p_P0l); // emb2
    BGEMM(p_P0h, p_P0l, p_t, 2, NN, D_HID, D_EMB, (const float*)0, 0, BFW0, BFW0); // conv1 xform
    k_init<<<NB, 256>>>();
    k_edge_hist<<<EB, 256>>>(ea, ep_w1, ep_b1, ep_w2, ep_b2, dst);
    k_dinv<<<NB, 256>>>();
    k_scan<<<1, 1024>>>();
    k_place<<<EB, 256>>>(src, dst);
    k_zero_pool<<<(NG * D_HID + 255) / 256, 256>>>();
    k_cnt<<<NB, 256>>>(batch);
    AGG(b_c[0], 1, p_P1h, p_P1l, (float*)0);                                      // conv1 agg

    BGEMM(p_P1h, p_P1l, p_t, 3, NN, D_HID, D_HID, (const float*)0, 0, BFW0, BFW0);
    AGG(b_c[1], 0, p_P0h, p_P0l, (float*)0);                                      // conv2
    BGEMM(p_P0h, p_P0l, p_t, 4, NN, D_HID, D_HID, (const float*)0, 0, BFW0, BFW0);
    AGG(b_c[2], 2, p_P1h, p_P1l, (float*)0);                                      // conv3
    BGEMM(p_P1h, p_P1l, p_t, 5, NN, D_HID, D_HID, (const float*)0, 0, BFW0, BFW0);
    AGG(b_c[3], 0, p_P0h, p_P0l, (float*)0);                                      // conv4
    BGEMM(p_P0h, p_P0l, p_t, 6, NN, D_HID, D_HID, (const float*)0, 0, BFW0, BFW0);
    AGG(b_c[4], 0, p_P1h, p_P1l, (float*)0);                                      // conv5
    BGEMM(p_P1h, p_P1l, p_t, 7, NN, D_HID, D_HID, (const float*)0, 0, BFW0, BFW0);
    AGG(b_c[5], 2, BFW0, BFW0, p_pool);                                           // conv6 + pool
#undef AGG
#undef BGEMM

    k_div<<<(NG * D_HID + 255) / 256, 256>>>();
    k_fc1<<<(NG * D_FC + 255) / 256, 256>>>(fc1_w, fc1_b);
    k_head<<<NG, 32>>>(head_w, head_b, (float*)d_out);
}

// round 11
// speedup vs baseline: 1.1751x; 1.0488x over previous
#include <cuda_runtime.h>
#include <cuda_bf16.h>
#include <stdint.h>
#include <math.h>

#define NN 40000
#define NE 640000
#define NG 64
#define F_IN 32
#define D_EMB 256
#define D_HID 512
#define D_FC 1024
#define N_CLS 10

// packed bf16 weight-plane segment offsets (elements), layout [k/32][n][k%32]
#define E0 8192
#define E1 73728
#define E2 204800
#define E3 466944
#define E4 729088
#define E5 991232
#define E6 1253376
#define E7 1515520

// ---------------- scratch ----------------
__device__ float g_ew[NE];
__device__ float g_deg[NN];
__device__ int   g_count[NN];
__device__ int   g_rowptr[NN + 1];
__device__ int   g_cursor[NN];
__device__ int   g_csrc[NE];
__device__ float g_cw[NE];
__device__ float g_t[NN * D_HID];
__device__ float g_skip[NN * D_HID];
__device__ float g_pool[NG * D_HID];
__device__ float g_cnt[NG];
__device__ float g_fc[NG * D_FC];
__device__ __nv_bfloat16 g_Bh[E7];
__device__ __nv_bfloat16 g_Bl[E7];
__device__ __nv_bfloat16 g_P0h[NN * D_HID];
__device__ __nv_bfloat16 g_P0l[NN * D_HID];
__device__ __nv_bfloat16 g_P1h[NN * D_HID];
__device__ __nv_bfloat16 g_P1l[NN * D_HID];

// ---------------- small kernels ----------------

__global__ void k_init() {
    int i = blockIdx.x * 256 + threadIdx.x;
    if (i < NN) { g_deg[i] = 1.0f; g_count[i] = 0; }
}

__global__ void k_prep(const float* __restrict__ w0, const float* __restrict__ w1,
                       const float* __restrict__ w2, const float* __restrict__ w3,
                       const float* __restrict__ w4, const float* __restrict__ w5,
                       const float* __restrict__ w6, const float* __restrict__ w7) {
    int i = blockIdx.x * 256 + threadIdx.x;
    if (i >= E7) return;
    const float* W; int N, base;
    if      (i < E0) { W = w0; N = 256; base = 0;  }
    else if (i < E1) { W = w1; N = 256; base = E0; }
    else if (i < E2) { W = w2; N = 512; base = E1; }
    else if (i < E3) { W = w3; N = 512; base = E2; }
    else if (i < E4) { W = w4; N = 512; base = E3; }
    else if (i < E5) { W = w5; N = 512; base = E4; }
    else if (i < E6) { W = w6; N = 512; base = E5; }
    else             { W = w7; N = 512; base = E6; }
    int li = i - base;
    int k = li / N, n = li - k * N;
    float v = W[li];
    __nv_bfloat16 hi = __float2bfloat16(v);
    __nv_bfloat16 lo = __float2bfloat16(v - __bfloat162float(hi));
    int pos = base + (k >> 5) * (N * 32) + n * 32 + (k & 31);
    g_Bh[pos] = hi;
    g_Bl[pos] = lo;
}

__global__ void k_splitx(const float* __restrict__ x,
                         __nv_bfloat16* __restrict__ ph, __nv_bfloat16* __restrict__ pl) {
    int i = blockIdx.x * 256 + threadIdx.x;
    if (i >= NN * F_IN) return;
    float v = x[i];
    __nv_bfloat16 h = __float2bfloat16(v);
    ph[i] = h;
    pl[i] = __float2bfloat16(v - __bfloat162float(h));
}

__global__ void k_edge_hist(const float* __restrict__ ea,
                            const float* __restrict__ w1, const float* __restrict__ b1,
                            const float* __restrict__ w2, const float* __restrict__ b2,
                            const int* __restrict__ dst) {
    int e = blockIdx.x * 256 + threadIdx.x;
    if (e >= NE) return;
    float a = ea[e];
    float s = b2[0];
#pragma unroll
    for (int j = 0; j < 64; j++) {
        float h = fmaxf(fmaf(a, __ldg(&w1[j]), __ldg(&b1[j])), 0.f);
        s = fmaf(h, __ldg(&w2[j]), s);
    }
    float sg = 1.f / (1.f + expf(-s));
    g_ew[e] = sg;
    int d = dst[e];
    atomicAdd(&g_deg[d], sg);
    atomicAdd(&g_count[d], 1);
}

__global__ void k_dinv() {
    int i = blockIdx.x * 256 + threadIdx.x;
    if (i < NN) g_deg[i] = rsqrtf(g_deg[i]);
}

__global__ void __launch_bounds__(1024) k_scan() {
    __shared__ int sp[1024];
    const int t = threadIdx.x;
    const int chunk = (NN + 1023) / 1024;
    const int beg = t * chunk;
    const int end = min(beg + chunk, NN);
    int s = 0;
    for (int i = beg; i < end; i++) s += g_count[i];
    sp[t] = s;
    __syncthreads();
    for (int off = 1; off < 1024; off <<= 1) {
        int v = sp[t];
        int u = (t >= off) ? sp[t - off] : 0;
        __syncthreads();
        sp[t] = v + u;
        __syncthreads();
    }
    int prefix = (t == 0) ? 0 : sp[t - 1];
    for (int i = beg; i < end; i++) {
        g_rowptr[i] = prefix;
        g_cursor[i] = prefix;
        prefix += g_count[i];
    }
    if (t == 1023) g_rowptr[NN] = prefix;
}

__global__ void k_place(const int* __restrict__ src, const int* __restrict__ dst) {
    int e = blockIdx.x * 256 + threadIdx.x;
    if (e >= NE) return;
    int s = src[e];
    float w = g_ew[e] * g_deg[s];
    int pos = atomicAdd(&g_cursor[dst[e]], 1);
    g_csrc[pos] = s;
    g_cw[pos] = w;
}

// ---------------- cp.async double-buffered bf16x3 tensor-core GEMM ----------------
// CTA 128x128, K-chunk 32, 2-stage pipeline. 8 warps of 64x32. Pitch 40 bf16 rows.
#define APITCH 40
#define PLANEB 10240
#define STAGEB (4 * PLANEB)
#define SMEMB  (2 * STAGEB)

__device__ __forceinline__ void cpa16(uint32_t d, const void* s) {
    asm volatile("cp.async.ca.shared.global [%0], [%1], 16;" :: "r"(d), "l"(s));
}
__device__ __forceinline__ void ldsm4(uint32_t addr, uint32_t* r) {
    asm volatile("ldmatrix.sync.aligned.m8n8.x4.shared.b16 {%0,%1,%2,%3}, [%4];"
                 : "=r"(r[0]), "=r"(r[1]), "=r"(r[2]), "=r"(r[3]) : "r"(addr));
}
__device__ __forceinline__ void mma16816(float* c, const uint32_t* a, uint32_t b0, uint32_t b1) {
    asm volatile("mma.sync.aligned.m16n8k16.row.col.f32.bf16.bf16.f32 "
                 "{%0,%1,%2,%3}, {%4,%5,%6,%7}, {%8,%9}, {%0,%1,%2,%3};"
                 : "+f"(c[0]), "+f"(c[1]), "+f"(c[2]), "+f"(c[3])
                 : "r"(a[0]), "r"(a[1]), "r"(a[2]), "r"(a[3]), "r"(b0), "r"(b1));
}

__global__ void __launch_bounds__(256, 2)
k_bgemm(const __nv_bfloat16* __restrict__ Ah, const __nv_bfloat16* __restrict__ Al,
        const __nv_bfloat16* __restrict__ Bh, const __nv_bfloat16* __restrict__ Bl,
        float* __restrict__ C, int M, int N, int K,
        const float* __restrict__ bias, int relu,
        __nv_bfloat16* __restrict__ outH, __nv_bfloat16* __restrict__ outL) {
    extern __shared__ __align__(128) char smem[];
    const int tid = threadIdx.x;
    const int lane = tid & 31;
    const int warp = tid >> 5;
    const int warpM = (warp & 1) * 64;
    const int warpN = (warp >> 1) * 32;
    const int rowBase = blockIdx.y * 128;
    const int colBase = blockIdx.x * 128;
    uint32_t sb;
    asm("{ .reg .u64 tt; cvta.to.shared.u64 tt, %1; cvt.u32.u64 %0, tt; }"
        : "=r"(sb) : "l"((const void*)smem));

    const int q = lane >> 3, r8 = lane & 7;
    const int aRowOff = r8 + (q & 1) * 8;
    const int aKOff = (q >> 1) * 8;
    const int bRowOff = r8 + (q >> 1) * 8;
    const int bKOff = (q & 1) * 8;
    uint32_t baseA[4], baseB[2];
#pragma unroll
    for (int mi = 0; mi < 4; mi++)
        baseA[mi] = sb + ((warpM + mi * 16 + aRowOff) * APITCH + aKOff) * 2;
#pragma unroll
    for (int bj = 0; bj < 2; bj++)
        baseB[bj] = sb + 2 * PLANEB + ((warpN + bj * 16 + bRowOff) * APITCH + bKOff) * 2;

    float acc[4][4][4] = {};
    const int nKC = K >> 5;

    auto prefetch = [&](int stage, int kc) {
        const uint32_t stb = sb + stage * STAGEB;
#pragma unroll
        for (int i = 0; i < 2; i++) {
            const int chunk = tid + 256 * i;
            const int row = chunk >> 2, o = chunk & 3;
            const int gar = min(rowBase + row, M - 1);
            const size_t aoff = (size_t)gar * K + kc * 32 + o * 8;
            const uint32_t sd = stb + row * 80 + o * 16;
            cpa16(sd, Ah + aoff);
            cpa16(sd + PLANEB, Al + aoff);
            const size_t boff = (size_t)kc * ((size_t)N * 32) + (size_t)(colBase + row) * 32 + o * 8;
            cpa16(sd + 2 * PLANEB, Bh + boff);
            cpa16(sd + 3 * PLANEB, Bl + boff);
        }
        asm volatile("cp.async.commit_group;");
    };

    prefetch(0, 0);
    for (int kc = 0; kc < nKC; kc++) {
        const bool more = (kc + 1 < nKC);
        if (more) prefetch((kc + 1) & 1, kc + 1);
        if (more) asm volatile("cp.async.wait_group 1;");
        else      asm volatile("cp.async.wait_group 0;");
        __syncthreads();
        const uint32_t stOff = (kc & 1) * STAGEB;
#pragma unroll
        for (int ks = 0; ks < 32; ks += 16) {
            uint32_t bh[8], bl[8];
            ldsm4(baseB[0] + stOff + ks * 2, bh);
            ldsm4(baseB[1] + stOff + ks * 2, bh + 4);
            ldsm4(baseB[0] + stOff + PLANEB + ks * 2, bl);
            ldsm4(baseB[1] + stOff + PLANEB + ks * 2, bl + 4);
#pragma unroll
            for (int mi = 0; mi < 4; mi++) {
                uint32_t ah[4], al[4];
                ldsm4(baseA[mi] + stOff + ks * 2, ah);
                mma16816(acc[mi][0], ah, bh[0], bh[1]);
                mma16816(acc[mi][1], ah, bh[2], bh[3]);
                mma16816(acc[mi][2], ah, bh[4], bh[5]);
                mma16816(acc[mi][3], ah, bh[6], bh[7]);
                mma16816(acc[mi][0], ah, bl[0], bl[1]);
                mma16816(acc[mi][1], ah, bl[2], bl[3]);
                mma16816(acc[mi][2], ah, bl[4], bl[5]);
                mma16816(acc[mi][3], ah, bl[6], bl[7]);
                ldsm4(baseA[mi] + stOff + PLANEB + ks * 2, al);
                mma16816(acc[mi][0], al, bh[0], bh[1]);
                mma16816(acc[mi][1], al, bh[2], bh[3]);
                mma16816(acc[mi][2], al, bh[4], bh[5]);
                mma16816(acc[mi][3], al, bh[6], bh[7]);
            }
        }
        __syncthreads();
    }

    // ---- epilogue (nullable C, optional bf16 plane output) ----
    const int g = lane >> 2, tg = lane & 3;
#pragma unroll
    for (int mi = 0; mi < 4; mi++) {
        const int row0 = rowBase + warpM + mi * 16 + g;
#pragma unroll
        for (int half = 0; half < 2; half++) {
            const int row = row0 + half * 8;
            if (row >= M) continue;
#pragma unroll
            for (int nj = 0; nj < 4; nj++) {
                const int col = colBase + warpN + nj * 8 + tg * 2;
                float v0 = acc[mi][nj][half * 2 + 0];
                float v1 = acc[mi][nj][half * 2 + 1];
                if (bias) { float2 bb = *(const float2*)&bias[col]; v0 += bb.x; v1 += bb.y; }
                if (relu) { v0 = fmaxf(v0, 0.f); v1 = fmaxf(v1, 0.f); }
                if (C) { float2 o = {v0, v1}; *(float2*)&C[(size_t)row * N + col] = o; }
                if (outH) {
                    __nv_bfloat162 h = __floats2bfloat162_rn(v0, v1);
                    __nv_bfloat162 l = __floats2bfloat162_rn(v0 - __bfloat162float(h.x),
                                                             v1 - __bfloat162float(h.y));
                    *(__nv_bfloat162*)&outH[(size_t)row * N + col] = h;
                    *(__nv_bfloat162*)&outL[(size_t)row * N + col] = l;
                }
            }
        }
    }
}

// ---- CSR aggregation: 1 node per 128-thread block, fused pooling option ----
__global__ void __launch_bounds__(128)
k_agg(const float4* __restrict__ t, const float* __restrict__ bias, int mode,
      float4* __restrict__ skip,
      __nv_bfloat16* __restrict__ outH, __nv_bfloat16* __restrict__ outL,
      const int* __restrict__ batch, float* __restrict__ pool) {
    const int node = blockIdx.x;
    const int c = threadIdx.x;
    const int beg = g_rowptr[node];
    const int end = g_rowptr[node + 1];
    const float di = g_deg[node];

    float ax = 0.f, ay = 0.f, az = 0.f, aw = 0.f;
    int j = beg;
    for (; j + 2 <= end; j += 2) {
        const int s0 = __ldg(&g_csrc[j]);
        const int s1 = __ldg(&g_csrc[j + 1]);
        const float w0 = __ldg(&g_cw[j]);
        const float w1 = __ldg(&g_cw[j + 1]);
        const float4 v0 = t[(size_t)s0 * 128 + c];
        const float4 v1 = t[(size_t)s1 * 128 + c];
        ax = fmaf(w0, v0.x, ax); ay = fmaf(w0, v0.y, ay);
        az = fmaf(w0, v0.z, az); aw = fmaf(w0, v0.w, aw);
        ax = fmaf(w1, v1.x, ax); ay = fmaf(w1, v1.y, ay);
        az = fmaf(w1, v1.z, az); aw = fmaf(w1, v1.w, aw);
    }
    if (j < end) {
        const int s0 = __ldg(&g_csrc[j]);
        const float w0 = __ldg(&g_cw[j]);
        const float4 v0 = t[(size_t)s0 * 128 + c];
        ax = fmaf(w0, v0.x, ax); ay = fmaf(w0, v0.y, ay);
        az = fmaf(w0, v0.z, az); aw = fmaf(w0, v0.w, aw);
    }
    const float4 vs = t[(size_t)node * 128 + c];
    const float4 bb = ((const float4*)bias)[c];
    float4 o;
    o.x = fmaf(di, fmaf(di, vs.x, ax), bb.x);
    o.y = fmaf(di, fmaf(di, vs.y, ay), bb.y);
    o.z = fmaf(di, fmaf(di, vs.z, az), bb.z);
    o.w = fmaf(di, fmaf(di, vs.w, aw), bb.w);
    float4 pv;
    pv.x = fmaxf(o.x, 0.f); pv.y = fmaxf(o.y, 0.f);
    pv.z = fmaxf(o.z, 0.f); pv.w = fmaxf(o.w, 0.f);
    if (mode == 1) {
        skip[(size_t)node * 128 + c] = pv;
    } else if (mode == 2) {
        float4 r = skip[(size_t)node * 128 + c];
        r.x += pv.x; r.y += pv.y; r.z += pv.z; r.w += pv.w;
        skip[(size_t)node * 128 + c] = r;
        pv = r;
    }
    if (outH) {
        const size_t off = (size_t)node * D_HID + c * 4;
        __nv_bfloat162 h0 = __floats2bfloat162_rn(pv.x, pv.y);
        __nv_bfloat162 l0 = __floats2bfloat162_rn(pv.x - __bfloat162float(h0.x),
                                                  pv.y - __bfloat162float(h0.y));
        __nv_bfloat162 h1 = __floats2bfloat162_rn(pv.z, pv.w);
        __nv_bfloat162 l1 = __floats2bfloat162_rn(pv.z - __bfloat162float(h1.x),
                                                  pv.w - __bfloat162float(h1.y));
        *(__nv_bfloat162*)&outH[off] = h0;
        *(__nv_bfloat162*)&outH[off + 2] = h1;
        *(__nv_bfloat162*)&outL[off] = l0;
        *(__nv_bfloat162*)&outL[off + 2] = l1;
    }
    if (pool) {
        const int b = batch[node];
        float* po = pool + b * D_HID + c * 4;
        atomicAdd(po + 0, pv.x);
        atomicAdd(po + 1, pv.y);
        atomicAdd(po + 2, pv.z);
        atomicAdd(po + 3, pv.w);
    }
}

// ---------------- pooling + head ----------------

__global__ void k_zero_pool() {
    int i = blockIdx.x * 256 + threadIdx.x;
    if (i < NG * D_HID) g_pool[i] = 0.f;
    if (i < NG) g_cnt[i] = 0.f;
}

__global__ void k_cnt(const int* __restrict__ batch) {
    int i = blockIdx.x * 256 + threadIdx.x;
    if (i < NN) atomicAdd(&g_cnt[batch[i]], 1.f);
}

__global__ void k_div() {
    int i = blockIdx.x * 256 + threadIdx.x;
    if (i >= NG * D_HID) return;
    g_pool[i] /= fmaxf(g_cnt[i >> 9], 1.f);
}

__global__ void k_fc1(const float* __restrict__ w, const float* __restrict__ b) {
    int idx = blockIdx.x * 256 + threadIdx.x;
    if (idx >= NG * D_FC) return;
    int j = idx & (D_FC - 1);
    int g = idx >> 10;
    float s = b[j];
    const float* p = g_pool + g * D_HID;
#pragma unroll 8
    for (int k = 0; k < D_HID; k++) s = fmaf(p[k], w[k * D_FC + j], s);
    g_fc[idx] = fmaxf(s, 0.f);
}

__global__ void k_head(const float* __restrict__ w, const float* __restrict__ b,
                       float* __restrict__ out) {
    int g = blockIdx.x;
    int j = threadIdx.x;
    if (j >= N_CLS) return;
    float s = b[j];
    const float* p = g_fc + g * D_FC;
    for (int k = 0; k < D_FC; k++) s = fmaf(p[k], w[k * N_CLS + j], s);
    out[g * N_CLS + j] = s;
}

// ---------------- launcher ----------------
extern "C" void kernel_launch(void* const* d_in, const int* in_sizes, int n_in,
                              void* d_out, int out_size) {
    const float* x      = (const float*)d_in[0];
    const int*   ei     = (const int*)d_in[1];
    const float* ea     = (const float*)d_in[2];
    const int*   batch  = (const int*)d_in[3];
    const float* emb_w1 = (const float*)d_in[4];
    const float* emb_b1 = (const float*)d_in[5];
    const float* emb_w2 = (const float*)d_in[6];
    const float* emb_b2 = (const float*)d_in[7];
    const float* ep_w1  = (const float*)d_in[8];
    const float* ep_b1  = (const float*)d_in[9];
    const float* ep_w2  = (const float*)d_in[10];
    const float* ep_b2  = (const float*)d_in[11];
    const float* w_c[6] = {(const float*)d_in[12], (const float*)d_in[14], (const float*)d_in[16],
                           (const float*)d_in[18], (const float*)d_in[20], (const float*)d_in[22]};
    const float* b_c[6] = {(const float*)d_in[13], (const float*)d_in[15], (const float*)d_in[17],
                           (const float*)d_in[19], (const float*)d_in[21], (const float*)d_in[23]};
    const float* fc1_w  = (const float*)d_in[24];
    const float* fc1_b  = (const float*)d_in[25];
    const float* head_w = (const float*)d_in[26];
    const float* head_b = (const float*)d_in[27];

    const int* src = ei;
    const int* dst = ei + NE;

    float *p_t, *p_skip, *p_pool;
    __nv_bfloat16 *p_Bh, *p_Bl, *p_P0h, *p_P0l, *p_P1h, *p_P1l;
    cudaGetSymbolAddress((void**)&p_t,    g_t);
    cudaGetSymbolAddress((void**)&p_skip, g_skip);
    cudaGetSymbolAddress((void**)&p_pool, g_pool);
    cudaGetSymbolAddress((void**)&p_Bh,   g_Bh);
    cudaGetSymbolAddress((void**)&p_Bl,   g_Bl);
    cudaGetSymbolAddress((void**)&p_P0h,  g_P0h);
    cudaGetSymbolAddress((void**)&p_P0l,  g_P0l);
    cudaGetSymbolAddress((void**)&p_P1h,  g_P1h);
    cudaGetSymbolAddress((void**)&p_P1l,  g_P1l);
    const int offW[8] = {0, E0, E1, E2, E3, E4, E5, E6};

    cudaFuncSetAttribute(k_bgemm, cudaFuncAttributeMaxDynamicSharedMemorySize, SMEMB);

    // side stream + events for overlapping the norm pipeline with the emb GEMM chain
    static cudaStream_t s2 = 0;
    static cudaEvent_t evFork = 0, evJoin = 0;
    if (!s2) {
        cudaStreamCreateWithFlags(&s2, cudaStreamNonBlocking);
        cudaEventCreateWithFlags(&evFork, cudaEventDisableTiming);
        cudaEventCreateWithFlags(&evJoin, cudaEventDisableTiming);
    }

    const int EB = (NE + 255) / 256;
    const int NB = (NN + 255) / 256;
    __nv_bfloat16* BFW0 = (__nv_bfloat16*)0;

#define BGEMM(AH, AL, Cout, OFFI, M_, N_, K_, BIAS, RELU, OH, OL)                            \
    k_bgemm<<<dim3((N_) / 128, ((M_) + 127) / 128), 256, SMEMB>>>(                           \
        (AH), (AL), p_Bh + offW[OFFI], p_Bl + offW[OFFI], (Cout), (M_), (N_), (K_),          \
        (BIAS), (RELU), (OH), (OL))
#define AGG(BIAS, MODE, OH, OL, POOL)                                                        \
    k_agg<<<NN, 128>>>((const float4*)p_t, (BIAS), (MODE), (float4*)p_skip,                  \
                       (OH), (OL), batch, (POOL))

    // fork: norm pipeline on s2, concurrent with weight prep + emb GEMM chain on stream 0
    cudaEventRecord(evFork, 0);
    cudaStreamWaitEvent(s2, evFork, 0);
    k_init<<<NB, 256, 0, s2>>>();
    k_edge_hist<<<EB, 256, 0, s2>>>(ea, ep_w1, ep_b1, ep_w2, ep_b2, dst);
    k_dinv<<<NB, 256, 0, s2>>>();
    k_scan<<<1, 1024, 0, s2>>>();
    k_place<<<EB, 256, 0, s2>>>(src, dst);
    k_zero_pool<<<(NG * D_HID + 255) / 256, 256, 0, s2>>>();
    k_cnt<<<NB, 256, 0, s2>>>(batch);
    cudaEventRecord(evJoin, s2);

    k_prep<<<(E7 + 255) / 256, 256>>>(emb_w1, emb_w2, w_c[0], w_c[1], w_c[2], w_c[3], w_c[4], w_c[5]);
    k_splitx<<<(NN * F_IN + 255) / 256, 256>>>(x, p_P0h, p_P0l);
    BGEMM(p_P0h, p_P0l, (float*)0, 0, NN, D_EMB, F_IN,  emb_b1, 1, p_P1h, p_P1l); // emb1
    BGEMM(p_P1h, p_P1l, (float*)0, 1, NN, D_EMB, D_EMB, emb_b2, 1, p_P0h, p_P0l); // emb2
    BGEMM(p_P0h, p_P0l, p_t, 2, NN, D_HID, D_EMB, (const float*)0, 0, BFW0, BFW0); // conv1 xform

    // join: aggregation needs the CSR/norm data
    cudaStreamWaitEvent(0, evJoin, 0);
    AGG(b_c[0], 1, p_P1h, p_P1l, (float*)0);                                      // conv1 agg

    BGEMM(p_P1h, p_P1l, p_t, 3, NN, D_HID, D_HID, (const float*)0, 0, BFW0, BFW0);
    AGG(b_c[1], 0, p_P0h, p_P0l, (float*)0);                                      // conv2
    BGEMM(p_P0h, p_P0l, p_t, 4, NN, D_HID, D_HID, (const float*)0, 0, BFW0, BFW0);
    AGG(b_c[2], 2, p_P1h, p_P1l, (float*)0);                                      // conv3
    BGEMM(p_P1h, p_P1l, p_t, 5, NN, D_HID, D_HID, (const float*)0, 0, BFW0, BFW0);
    AGG(b_c[3], 0, p_P0h, p_P0l, (float*)0);                                      // conv4
    BGEMM(p_P0h, p_P0l, p_t, 6, NN, D_HID, D_HID, (const float*)0, 0, BFW0, BFW0);
    AGG(b_c[4], 0, p_P1h, p_P1l, (float*)0);                                      // conv5
    BGEMM(p_P1h, p_P1l, p_t, 7, NN, D_HID, D_HID, (const float*)0, 0, BFW0, BFW0);
    AGG(b_c[5], 2, BFW0, BFW0, p_pool);                                           // conv6 + pool
#undef AGG
#undef BGEMM

    k_div<<<(NG * D_HID + 255) / 256, 256>>>();
    k_fc1<<<(NG * D_FC + 255) / 256, 256>>>(fc1_w, fc1_b);
    k_head<<<NG, 32>>>(head_w, head_b, (float*)d_out);
}

// round 12
// speedup vs baseline: 1.1912x; 1.0137x over previous
#include <cuda_runtime.h>
#include <cuda_bf16.h>
#include <stdint.h>
#include <math.h>

#define NN 40000
#define NE 640000
#define NG 64
#define F_IN 32
#define D_EMB 256
#define D_HID 512
#define D_FC 1024
#define N_CLS 10

// packed bf16 weight-plane segment offsets (elements), layout [k/32][n][k%32]
#define E0 8192
#define E1 73728
#define E2 204800
#define E3 466944
#define E4 729088
#define E5 991232
#define E6 1253376
#define E7 1515520

// ---------------- scratch ----------------
__device__ float g_ew[NE];
__device__ float g_deg[NN];
__device__ int   g_count[NN];
__device__ int   g_rowptr[NN + 1];
__device__ int   g_cursor[NN];
__device__ int   g_csrc[NE];
__device__ float g_cw[NE];
__device__ float g_t[NN * D_HID];      // conv2-6: fp32 transformed; conv1: reused as bf16 agg planes
__device__ float g_skip[NN * D_HID];
__device__ float g_pool[NG * D_HID];
__device__ float g_cnt[NG];
__device__ float g_fc[NG * D_FC];
__device__ __nv_bfloat16 g_Bh[E7];
__device__ __nv_bfloat16 g_Bl[E7];
__device__ __nv_bfloat16 g_P0h[NN * D_HID];
__device__ __nv_bfloat16 g_P0l[NN * D_HID];
__device__ __nv_bfloat16 g_P1h[NN * D_HID];
__device__ __nv_bfloat16 g_P1l[NN * D_HID];

// ---------------- small kernels ----------------

__global__ void k_init() {
    int i = blockIdx.x * 256 + threadIdx.x;
    if (i < NN) { g_deg[i] = 1.0f; g_count[i] = 0; }
}

__global__ void k_prep(const float* __restrict__ w0, const float* __restrict__ w1,
                       const float* __restrict__ w2, const float* __restrict__ w3,
                       const float* __restrict__ w4, const float* __restrict__ w5,
                       const float* __restrict__ w6, const float* __restrict__ w7) {
    int i = blockIdx.x * 256 + threadIdx.x;
    if (i >= E7) return;
    const float* W; int N, base;
    if      (i < E0) { W = w0; N = 256; base = 0;  }
    else if (i < E1) { W = w1; N = 256; base = E0; }
    else if (i < E2) { W = w2; N = 512; base = E1; }
    else if (i < E3) { W = w3; N = 512; base = E2; }
    else if (i < E4) { W = w4; N = 512; base = E3; }
    else if (i < E5) { W = w5; N = 512; base = E4; }
    else if (i < E6) { W = w6; N = 512; base = E5; }
    else             { W = w7; N = 512; base = E6; }
    int li = i - base;
    int k = li / N, n = li - k * N;
    float v = W[li];
    __nv_bfloat16 hi = __float2bfloat16(v);
    __nv_bfloat16 lo = __float2bfloat16(v - __bfloat162float(hi));
    int pos = base + (k >> 5) * (N * 32) + n * 32 + (k & 31);
    g_Bh[pos] = hi;
    g_Bl[pos] = lo;
}

__global__ void k_splitx(const float* __restrict__ x,
                         __nv_bfloat16* __restrict__ ph, __nv_bfloat16* __restrict__ pl) {
    int i = blockIdx.x * 256 + threadIdx.x;
    if (i >= NN * F_IN) return;
    float v = x[i];
    __nv_bfloat16 h = __float2bfloat16(v);
    ph[i] = h;
    pl[i] = __float2bfloat16(v - __bfloat162float(h));
}

__global__ void k_edge_hist(const float* __restrict__ ea,
                            const float* __restrict__ w1, const float* __restrict__ b1,
                            const float* __restrict__ w2, const float* __restrict__ b2,
                            const int* __restrict__ dst) {
    int e = blockIdx.x * 256 + threadIdx.x;
    if (e >= NE) return;
    float a = ea[e];
    float s = b2[0];
#pragma unroll
    for (int j = 0; j < 64; j++) {
        float h = fmaxf(fmaf(a, __ldg(&w1[j]), __ldg(&b1[j])), 0.f);
        s = fmaf(h, __ldg(&w2[j]), s);
    }
    float sg = 1.f / (1.f + expf(-s));
    g_ew[e] = sg;
    int d = dst[e];
    atomicAdd(&g_deg[d], sg);
    atomicAdd(&g_count[d], 1);
}

__global__ void k_dinv() {
    int i = blockIdx.x * 256 + threadIdx.x;
    if (i < NN) g_deg[i] = rsqrtf(g_deg[i]);
}

__global__ void __launch_bounds__(1024) k_scan() {
    __shared__ int sp[1024];
    const int t = threadIdx.x;
    const int chunk = (NN + 1023) / 1024;
    const int beg = t * chunk;
    const int end = min(beg + chunk, NN);
    int s = 0;
    for (int i = beg; i < end; i++) s += g_count[i];
    sp[t] = s;
    __syncthreads();
    for (int off = 1; off < 1024; off <<= 1) {
        int v = sp[t];
        int u = (t >= off) ? sp[t - off] : 0;
        __syncthreads();
        sp[t] = v + u;
        __syncthreads();
    }
    int prefix = (t == 0) ? 0 : sp[t - 1];
    for (int i = beg; i < end; i++) {
        g_rowptr[i] = prefix;
        g_cursor[i] = prefix;
        prefix += g_count[i];
    }
    if (t == 1023) g_rowptr[NN] = prefix;
}

__global__ void k_place(const int* __restrict__ src, const int* __restrict__ dst) {
    int e = blockIdx.x * 256 + threadIdx.x;
    if (e >= NE) return;
    int s = src[e];
    float w = g_ew[e] * g_deg[s];
    int pos = atomicAdd(&g_cursor[dst[e]], 1);
    g_csrc[pos] = s;
    g_cw[pos] = w;
}

// ---------------- cp.async double-buffered bf16x3 tensor-core GEMM ----------------
#define APITCH 40
#define PLANEB 10240
#define STAGEB (4 * PLANEB)
#define SMEMB  (2 * STAGEB)

__device__ __forceinline__ void cpa16(uint32_t d, const void* s) {
    asm volatile("cp.async.ca.shared.global [%0], [%1], 16;" :: "r"(d), "l"(s));
}
__device__ __forceinline__ void ldsm4(uint32_t addr, uint32_t* r) {
    asm volatile("ldmatrix.sync.aligned.m8n8.x4.shared.b16 {%0,%1,%2,%3}, [%4];"
                 : "=r"(r[0]), "=r"(r[1]), "=r"(r[2]), "=r"(r[3]) : "r"(addr));
}
__device__ __forceinline__ void mma16816(float* c, const uint32_t* a, uint32_t b0, uint32_t b1) {
    asm volatile("mma.sync.aligned.m16n8k16.row.col.f32.bf16.bf16.f32 "
                 "{%0,%1,%2,%3}, {%4,%5,%6,%7}, {%8,%9}, {%0,%1,%2,%3};"
                 : "+f"(c[0]), "+f"(c[1]), "+f"(c[2]), "+f"(c[3])
                 : "r"(a[0]), "r"(a[1]), "r"(a[2]), "r"(a[3]), "r"(b0), "r"(b1));
}

__global__ void __launch_bounds__(256, 2)
k_bgemm(const __nv_bfloat16* __restrict__ Ah, const __nv_bfloat16* __restrict__ Al,
        const __nv_bfloat16* __restrict__ Bh, const __nv_bfloat16* __restrict__ Bl,
        float* __restrict__ C, int M, int N, int K,
        const float* __restrict__ bias, int relu,
        __nv_bfloat16* __restrict__ outH, __nv_bfloat16* __restrict__ outL) {
    extern __shared__ __align__(128) char smem[];
    const int tid = threadIdx.x;
    const int lane = tid & 31;
    const int warp = tid >> 5;
    const int warpM = (warp & 1) * 64;
    const int warpN = (warp >> 1) * 32;
    const int rowBase = blockIdx.y * 128;
    const int colBase = blockIdx.x * 128;
    uint32_t sb;
    asm("{ .reg .u64 tt; cvta.to.shared.u64 tt, %1; cvt.u32.u64 %0, tt; }"
        : "=r"(sb) : "l"((const void*)smem));

    const int q = lane >> 3, r8 = lane & 7;
    const int aRowOff = r8 + (q & 1) * 8;
    const int aKOff = (q >> 1) * 8;
    const int bRowOff = r8 + (q >> 1) * 8;
    const int bKOff = (q & 1) * 8;
    uint32_t baseA[4], baseB[2];
#pragma unroll
    for (int mi = 0; mi < 4; mi++)
        baseA[mi] = sb + ((warpM + mi * 16 + aRowOff) * APITCH + aKOff) * 2;
#pragma unroll
    for (int bj = 0; bj < 2; bj++)
        baseB[bj] = sb + 2 * PLANEB + ((warpN + bj * 16 + bRowOff) * APITCH + bKOff) * 2;

    float acc[4][4][4] = {};
    const int nKC = K >> 5;

    auto prefetch = [&](int stage, int kc) {
        const uint32_t stb = sb + stage * STAGEB;
#pragma unroll
        for (int i = 0; i < 2; i++) {
            const int chunk = tid + 256 * i;
            const int row = chunk >> 2, o = chunk & 3;
            const int gar = min(rowBase + row, M - 1);
            const size_t aoff = (size_t)gar * K + kc * 32 + o * 8;
            const uint32_t sd = stb + row * 80 + o * 16;
            cpa16(sd, Ah + aoff);
            cpa16(sd + PLANEB, Al + aoff);
            const size_t boff = (size_t)kc * ((size_t)N * 32) + (size_t)(colBase + row) * 32 + o * 8;
            cpa16(sd + 2 * PLANEB, Bh + boff);
            cpa16(sd + 3 * PLANEB, Bl + boff);
        }
        asm volatile("cp.async.commit_group;");
    };

    prefetch(0, 0);
    for (int kc = 0; kc < nKC; kc++) {
        const bool more = (kc + 1 < nKC);
        if (more) prefetch((kc + 1) & 1, kc + 1);
        if (more) asm volatile("cp.async.wait_group 1;");
        else      asm volatile("cp.async.wait_group 0;");
        __syncthreads();
        const uint32_t stOff = (kc & 1) * STAGEB;
#pragma unroll
        for (int ks = 0; ks < 32; ks += 16) {
            uint32_t bh[8], bl[8];
            ldsm4(baseB[0] + stOff + ks * 2, bh);
            ldsm4(baseB[1] + stOff + ks * 2, bh + 4);
            ldsm4(baseB[0] + stOff + PLANEB + ks * 2, bl);
            ldsm4(baseB[1] + stOff + PLANEB + ks * 2, bl + 4);
#pragma unroll
            for (int mi = 0; mi < 4; mi++) {
                uint32_t ah[4], al[4];
                ldsm4(baseA[mi] + stOff + ks * 2, ah);
                mma16816(acc[mi][0], ah, bh[0], bh[1]);
                mma16816(acc[mi][1], ah, bh[2], bh[3]);
                mma16816(acc[mi][2], ah, bh[4], bh[5]);
                mma16816(acc[mi][3], ah, bh[6], bh[7]);
                mma16816(acc[mi][0], ah, bl[0], bl[1]);
                mma16816(acc[mi][1], ah, bl[2], bl[3]);
                mma16816(acc[mi][2], ah, bl[4], bl[5]);
                mma16816(acc[mi][3], ah, bl[6], bl[7]);
                ldsm4(baseA[mi] + stOff + PLANEB + ks * 2, al);
                mma16816(acc[mi][0], al, bh[0], bh[1]);
                mma16816(acc[mi][1], al, bh[2], bh[3]);
                mma16816(acc[mi][2], al, bh[4], bh[5]);
                mma16816(acc[mi][3], al, bh[6], bh[7]);
            }
        }
        __syncthreads();
    }

    // ---- epilogue (nullable C, optional bf16 plane output) ----
    const int g = lane >> 2, tg = lane & 3;
#pragma unroll
    for (int mi = 0; mi < 4; mi++) {
        const int row0 = rowBase + warpM + mi * 16 + g;
#pragma unroll
        for (int half = 0; half < 2; half++) {
            const int row = row0 + half * 8;
            if (row >= M) continue;
#pragma unroll
            for (int nj = 0; nj < 4; nj++) {
                const int col = colBase + warpN + nj * 8 + tg * 2;
                float v0 = acc[mi][nj][half * 2 + 0];
                float v1 = acc[mi][nj][half * 2 + 1];
                if (bias) { float2 bb = *(const float2*)&bias[col]; v0 += bb.x; v1 += bb.y; }
                if (relu) { v0 = fmaxf(v0, 0.f); v1 = fmaxf(v1, 0.f); }
                if (C) { float2 o = {v0, v1}; *(float2*)&C[(size_t)row * N + col] = o; }
                if (outH) {
                    __nv_bfloat162 h = __floats2bfloat162_rn(v0, v1);
                    __nv_bfloat162 l = __floats2bfloat162_rn(v0 - __bfloat162float(h.x),
                                                             v1 - __bfloat162float(h.y));
                    *(__nv_bfloat162*)&outH[(size_t)row * N + col] = h;
                    *(__nv_bfloat162*)&outL[(size_t)row * N + col] = l;
                }
            }
        }
    }
}

// ---- conv1: aggregate the 256-dim emb2 planes BEFORE the GEMM (agg commutes with W) ----
// a[node] = dinv*(sum_e w_e h[src_e] + dinv*h[node]), h = hi + lo. Output as planes.
__global__ void __launch_bounds__(64)
k_agg256(const __nv_bfloat16* __restrict__ hH, const __nv_bfloat16* __restrict__ hL,
         __nv_bfloat16* __restrict__ outH, __nv_bfloat16* __restrict__ outL) {
    const int node = blockIdx.x;
    const int c = threadIdx.x;  // owns 4 elements
    const int beg = g_rowptr[node];
    const int end = g_rowptr[node + 1];
    const float di = g_deg[node];

    float a0 = 0.f, a1 = 0.f, a2 = 0.f, a3 = 0.f;
    for (int j = beg; j < end; j++) {
        const int s = __ldg(&g_csrc[j]);
        const float w = __ldg(&g_cw[j]);
        const size_t off = (size_t)s * D_EMB + c * 4;
        const __nv_bfloat162 h0 = *(const __nv_bfloat162*)&hH[off];
        const __nv_bfloat162 h1 = *(const __nv_bfloat162*)&hH[off + 2];
        const __nv_bfloat162 l0 = *(const __nv_bfloat162*)&hL[off];
        const __nv_bfloat162 l1 = *(const __nv_bfloat162*)&hL[off + 2];
        a0 = fmaf(w, __bfloat162float(h0.x) + __bfloat162float(l0.x), a0);
        a1 = fmaf(w, __bfloat162float(h0.y) + __bfloat162float(l0.y), a1);
        a2 = fmaf(w, __bfloat162float(h1.x) + __bfloat162float(l1.x), a2);
        a3 = fmaf(w, __bfloat162float(h1.y) + __bfloat162float(l1.y), a3);
    }
    {
        const size_t off = (size_t)node * D_EMB + c * 4;
        const __nv_bfloat162 h0 = *(const __nv_bfloat162*)&hH[off];
        const __nv_bfloat162 h1 = *(const __nv_bfloat162*)&hH[off + 2];
        const __nv_bfloat162 l0 = *(const __nv_bfloat162*)&hL[off];
        const __nv_bfloat162 l1 = *(const __nv_bfloat162*)&hL[off + 2];
        a0 = fmaf(di, __bfloat162float(h0.x) + __bfloat162float(l0.x), a0);
        a1 = fmaf(di, __bfloat162float(h0.y) + __bfloat162float(l0.y), a1);
        a2 = fmaf(di, __bfloat162float(h1.x) + __bfloat162float(l1.x), a2);
        a3 = fmaf(di, __bfloat162float(h1.y) + __bfloat162float(l1.y), a3);
    }
    a0 *= di; a1 *= di; a2 *= di; a3 *= di;
    const size_t off = (size_t)node * D_EMB + c * 4;
    __nv_bfloat162 H0 = __floats2bfloat162_rn(a0, a1);
    __nv_bfloat162 L0 = __floats2bfloat162_rn(a0 - __bfloat162float(H0.x),
                                              a1 - __bfloat162float(H0.y));
    __nv_bfloat162 H1 = __floats2bfloat162_rn(a2, a3);
    __nv_bfloat162 L1 = __floats2bfloat162_rn(a2 - __bfloat162float(H1.x),
                                              a3 - __bfloat162float(H1.y));
    *(__nv_bfloat162*)&outH[off] = H0;
    *(__nv_bfloat162*)&outH[off + 2] = H1;
    *(__nv_bfloat162*)&outL[off] = L0;
    *(__nv_bfloat162*)&outL[off + 2] = L1;
}

// ---- CSR aggregation (conv2-6): 1 node per 128-thread block, fused pooling option ----
__global__ void __launch_bounds__(128)
k_agg(const float4* __restrict__ t, const float* __restrict__ bias, int mode,
      float4* __restrict__ skip,
      __nv_bfloat16* __restrict__ outH, __nv_bfloat16* __restrict__ outL,
      const int* __restrict__ batch, float* __restrict__ pool) {
    const int node = blockIdx.x;
    const int c = threadIdx.x;
    const int beg = g_rowptr[node];
    const int end = g_rowptr[node + 1];
    const float di = g_deg[node];

    float ax = 0.f, ay = 0.f, az = 0.f, aw = 0.f;
    int j = beg;
    for (; j + 2 <= end; j += 2) {
        const int s0 = __ldg(&g_csrc[j]);
        const int s1 = __ldg(&g_csrc[j + 1]);
        const float w0 = __ldg(&g_cw[j]);
        const float w1 = __ldg(&g_cw[j + 1]);
        const float4 v0 = t[(size_t)s0 * 128 + c];
        const float4 v1 = t[(size_t)s1 * 128 + c];
        ax = fmaf(w0, v0.x, ax); ay = fmaf(w0, v0.y, ay);
        az = fmaf(w0, v0.z, az); aw = fmaf(w0, v0.w, aw);
        ax = fmaf(w1, v1.x, ax); ay = fmaf(w1, v1.y, ay);
        az = fmaf(w1, v1.z, az); aw = fmaf(w1, v1.w, aw);
    }
    if (j < end) {
        const int s0 = __ldg(&g_csrc[j]);
        const float w0 = __ldg(&g_cw[j]);
        const float4 v0 = t[(size_t)s0 * 128 + c];
        ax = fmaf(w0, v0.x, ax); ay = fmaf(w0, v0.y, ay);
        az = fmaf(w0, v0.z, az); aw = fmaf(w0, v0.w, aw);
    }
    const float4 vs = t[(size_t)node * 128 + c];
    const float4 bb = ((const float4*)bias)[c];
    float4 o;
    o.x = fmaf(di, fmaf(di, vs.x, ax), bb.x);
    o.y = fmaf(di, fmaf(di, vs.y, ay), bb.y);
    o.z = fmaf(di, fmaf(di, vs.z, az), bb.z);
    o.w = fmaf(di, fmaf(di, vs.w, aw), bb.w);
    float4 pv;
    pv.x = fmaxf(o.x, 0.f); pv.y = fmaxf(o.y, 0.f);
    pv.z = fmaxf(o.z, 0.f); pv.w = fmaxf(o.w, 0.f);
    if (mode == 1) {
        skip[(size_t)node * 128 + c] = pv;
    } else if (mode == 2) {
        float4 r = skip[(size_t)node * 128 + c];
        r.x += pv.x; r.y += pv.y; r.z += pv.z; r.w += pv.w;
        skip[(size_t)node * 128 + c] = r;
        pv = r;
    }
    if (outH) {
        const size_t off = (size_t)node * D_HID + c * 4;
        __nv_bfloat162 h0 = __floats2bfloat162_rn(pv.x, pv.y);
        __nv_bfloat162 l0 = __floats2bfloat162_rn(pv.x - __bfloat162float(h0.x),
                                                  pv.y - __bfloat162float(h0.y));
        __nv_bfloat162 h1 = __floats2bfloat162_rn(pv.z, pv.w);
        __nv_bfloat162 l1 = __floats2bfloat162_rn(pv.z - __bfloat162float(h1.x),
                                                  pv.w - __bfloat162float(h1.y));
        *(__nv_bfloat162*)&outH[off] = h0;
        *(__nv_bfloat162*)&outH[off + 2] = h1;
        *(__nv_bfloat162*)&outL[off] = l0;
        *(__nv_bfloat162*)&outL[off + 2] = l1;
    }
    if (pool) {
        const int b = batch[node];
        float* po = pool + b * D_HID + c * 4;
        atomicAdd(po + 0, pv.x);
        atomicAdd(po + 1, pv.y);
        atomicAdd(po + 2, pv.z);
        atomicAdd(po + 3, pv.w);
    }
}

// ---------------- pooling + head ----------------

__global__ void k_zero_pool() {
    int i = blockIdx.x * 256 + threadIdx.x;
    if (i < NG * D_HID) g_pool[i] = 0.f;
    if (i < NG) g_cnt[i] = 0.f;
}

__global__ void k_cnt(const int* __restrict__ batch) {
    int i = blockIdx.x * 256 + threadIdx.x;
    if (i < NN) atomicAdd(&g_cnt[batch[i]], 1.f);
}

__global__ void k_div() {
    int i = blockIdx.x * 256 + threadIdx.x;
    if (i >= NG * D_HID) return;
    g_pool[i] /= fmaxf(g_cnt[i >> 9], 1.f);
}

__global__ void k_fc1(const float* __restrict__ w, const float* __restrict__ b) {
    int idx = blockIdx.x * 256 + threadIdx.x;
    if (idx >= NG * D_FC) return;
    int j = idx & (D_FC - 1);
    int g = idx >> 10;
    float s = b[j];
    const float* p = g_pool + g * D_HID;
#pragma unroll 8
    for (int k = 0; k < D_HID; k++) s = fmaf(p[k], w[k * D_FC + j], s);
    g_fc[idx] = fmaxf(s, 0.f);
}

__global__ void k_head(const float* __restrict__ w, const float* __restrict__ b,
                       float* __restrict__ out) {
    int g = blockIdx.x;
    int j = threadIdx.x;
    if (j >= N_CLS) return;
    float s = b[j];
    const float* p = g_fc + g * D_FC;
    for (int k = 0; k < D_FC; k++) s = fmaf(p[k], w[k * N_CLS + j], s);
    out[g * N_CLS + j] = s;
}

// ---------------- launcher ----------------
extern "C" void kernel_launch(void* const* d_in, const int* in_sizes, int n_in,
                              void* d_out, int out_size) {
    const float* x      = (const float*)d_in[0];
    const int*   ei     = (const int*)d_in[1];
    const float* ea     = (const float*)d_in[2];
    const int*   batch  = (const int*)d_in[3];
    const float* emb_w1 = (const float*)d_in[4];
    const float* emb_b1 = (const float*)d_in[5];
    const float* emb_w2 = (const float*)d_in[6];
    const float* emb_b2 = (const float*)d_in[7];
    const float* ep_w1  = (const float*)d_in[8];
    const float* ep_b1  = (const float*)d_in[9];
    const float* ep_w2  = (const float*)d_in[10];
    const float* ep_b2  = (const float*)d_in[11];
    const float* w_c[6] = {(const float*)d_in[12], (const float*)d_in[14], (const float*)d_in[16],
                           (const float*)d_in[18], (const float*)d_in[20], (const float*)d_in[22]};
    const float* b_c[6] = {(const float*)d_in[13], (const float*)d_in[15], (const float*)d_in[17],
                           (const float*)d_in[19], (const float*)d_in[21], (const float*)d_in[23]};
    const float* fc1_w  = (const float*)d_in[24];
    const float* fc1_b  = (const float*)d_in[25];
    const float* head_w = (const float*)d_in[26];
    const float* head_b = (const float*)d_in[27];

    const int* src = ei;
    const int* dst = ei + NE;

    float *p_t, *p_skip, *p_pool;
    __nv_bfloat16 *p_Bh, *p_Bl, *p_P0h, *p_P0l, *p_P1h, *p_P1l;
    cudaGetSymbolAddress((void**)&p_t,    g_t);
    cudaGetSymbolAddress((void**)&p_skip, g_skip);
    cudaGetSymbolAddress((void**)&p_pool, g_pool);
    cudaGetSymbolAddress((void**)&p_Bh,   g_Bh);
    cudaGetSymbolAddress((void**)&p_Bl,   g_Bl);
    cudaGetSymbolAddress((void**)&p_P0h,  g_P0h);
    cudaGetSymbolAddress((void**)&p_P0l,  g_P0l);
    cudaGetSymbolAddress((void**)&p_P1h,  g_P1h);
    cudaGetSymbolAddress((void**)&p_P1l,  g_P1l);
    // conv1 aggregated planes alias the (otherwise idle) g_t buffer
    __nv_bfloat16* p_aH = (__nv_bfloat16*)p_t;
    __nv_bfloat16* p_aL = (__nv_bfloat16*)p_t + (size_t)NN * D_EMB;
    const int offW[8] = {0, E0, E1, E2, E3, E4, E5, E6};

    cudaFuncSetAttribute(k_bgemm, cudaFuncAttributeMaxDynamicSharedMemorySize, SMEMB);

    static cudaStream_t s2 = 0;
    static cudaEvent_t evFork = 0, evJoin = 0;
    if (!s2) {
        cudaStreamCreateWithFlags(&s2, cudaStreamNonBlocking);
        cudaEventCreateWithFlags(&evFork, cudaEventDisableTiming);
        cudaEventCreateWithFlags(&evJoin, cudaEventDisableTiming);
    }

    const int EB = (NE + 255) / 256;
    const int NB = (NN + 255) / 256;
    __nv_bfloat16* BFW0 = (__nv_bfloat16*)0;

#define BGEMM(AH, AL, Cout, OFFI, M_, N_, K_, BIAS, RELU, OH, OL)                            \
    k_bgemm<<<dim3((N_) / 128, ((M_) + 127) / 128), 256, SMEMB>>>(                           \
        (AH), (AL), p_Bh + offW[OFFI], p_Bl + offW[OFFI], (Cout), (M_), (N_), (K_),          \
        (BIAS), (RELU), (OH), (OL))
#define AGG(BIAS, MODE, OH, OL, POOL)                                                        \
    k_agg<<<NN, 128>>>((const float4*)p_t, (BIAS), (MODE), (float4*)p_skip,                  \
                       (OH), (OL), batch, (POOL))

    // fork: norm pipeline on s2, concurrent with weight prep + emb GEMM chain on stream 0
    cudaEventRecord(evFork, 0);
    cudaStreamWaitEvent(s2, evFork, 0);
    k_init<<<NB, 256, 0, s2>>>();
    k_edge_hist<<<EB, 256, 0, s2>>>(ea, ep_w1, ep_b1, ep_w2, ep_b2, dst);
    k_dinv<<<NB, 256, 0, s2>>>();
    k_scan<<<1, 1024, 0, s2>>>();
    k_place<<<EB, 256, 0, s2>>>(src, dst);
    k_zero_pool<<<(NG * D_HID + 255) / 256, 256, 0, s2>>>();
    k_cnt<<<NB, 256, 0, s2>>>(batch);
    cudaEventRecord(evJoin, s2);

    k_prep<<<(E7 + 255) / 256, 256>>>(emb_w1, emb_w2, w_c[0], w_c[1], w_c[2], w_c[3], w_c[4], w_c[5]);
    k_splitx<<<(NN * F_IN + 255) / 256, 256>>>(x, p_P0h, p_P0l);
    BGEMM(p_P0h, p_P0l, (float*)0, 0, NN, D_EMB, F_IN,  emb_b1, 1, p_P1h, p_P1l); // emb1
    BGEMM(p_P1h, p_P1l, (float*)0, 1, NN, D_EMB, D_EMB, emb_b2, 1, p_P0h, p_P0l); // emb2

    // join: conv1 agg needs CSR/norm data. Aggregate 256-dim planes, then GEMM.
    cudaStreamWaitEvent(0, evJoin, 0);
    k_agg256<<<NN, 64>>>(p_P0h, p_P0l, p_aH, p_aL);
    // conv1 GEMM: skip = relu(a W + b), planes P1 = skip
    BGEMM(p_aH, p_aL, p_skip, 2, NN, D_HID, D_EMB, b_c[0], 1, p_P1h, p_P1l);

    BGEMM(p_P1h, p_P1l, p_t, 3, NN, D_HID, D_HID, (const float*)0, 0, BFW0, BFW0);
    AGG(b_c[1], 0, p_P0h, p_P0l, (float*)0);                                      // conv2
    BGEMM(p_P0h, p_P0l, p_t, 4, NN, D_HID, D_HID, (const float*)0, 0, BFW0, BFW0);
    AGG(b_c[2], 2, p_P1h, p_P1l, (float*)0);                                      // conv3
    BGEMM(p_P1h, p_P1l, p_t, 5, NN, D_HID, D_HID, (const float*)0, 0, BFW0, BFW0);
    AGG(b_c[3], 0, p_P0h, p_P0l, (float*)0);                                      // conv4
    BGEMM(p_P0h, p_P0l, p_t, 6, NN, D_HID, D_HID, (const float*)0, 0, BFW0, BFW0);
    AGG(b_c[4], 0, p_P1h, p_P1l, (float*)0);                                      // conv5
    BGEMM(p_P1h, p_P1l, p_t, 7, NN, D_HID, D_HID, (const float*)0, 0, BFW0, BFW0);
    AGG(b_c[5], 2, BFW0, BFW0, p_pool);                                           // conv6 + pool
#undef AGG
#undef BGEMM

    k_div<<<(NG * D_HID + 255) / 256, 256>>>();
    k_fc1<<<(NG * D_FC + 255) / 256, 256>>>(fc1_w, fc1_b);
    k_head<<<NG, 32>>>(head_w, head_b, (float*)d_out);
}